// round 3
// baseline (speedup 1.0000x reference)
#include <cuda_runtime.h>
#include <math.h>

#define NN 1500
#define NE 1200
#define NB 96
#define KC 60
#define KSPLIT 25
#define NSTEPS 60
#define DEPTH 3     // prefetch depth; KC = 60 = 20 blocks of 3

typedef unsigned long long u64;

// ---------------- static device buffers (no allocations allowed) ----------------
__device__ float d_W1[(size_t)NN * NN];           // [j][i] = W[i][j]       9MB
__device__ float d_W2[(size_t)NN * NN];           // [j][i] = W[i][j]^2     9MB
__device__ float d_mean[NB * NN];                 // [b][i]
__device__ float d_rateA[NB * NN];                // ping
__device__ float d_rateB[NB * NN];                // pong
__device__ float d_pmu[KSPLIT * NB * NN];         // split-K partials of rate@W^T
__device__ float d_ps2[KSPLIT * NB * NN];         // split-K partials of rate@(W^2)^T

__constant__ float c_contr[8] = {0.0f, 0.0432773f, 0.103411f, 0.186966f,
                                 0.303066f, 0.464386f, 0.68854f, 1.0f};

// ---------------- helpers ----------------
__device__ __forceinline__ float prefv(int n) {
    const float se = 179.99f / 1200.0f;
    const float si = 179.99f / 300.0f;
    return (n < NE) ? (float)n * se : (float)(n - NE) * si;
}

__device__ __forceinline__ u64 pack2(float x, float y) {
    u64 r;
    asm("mov.b64 %0, {%1,%2};" : "=l"(r) : "f"(x), "f"(y));
    return r;
}
// packed dual FMA: d.lo += a.lo*b.lo ; d.hi += a.hi*b.hi   (FFMA2, sm_103a)
__device__ __forceinline__ void fma2(u64& d, u64 a, u64 b) {
    asm("fma.rn.f32x2 %0, %1, %2, %0;" : "+l"(d) : "l"(a), "l"(b));
}

// ---------------- Ricciardi transfer ----------------
__device__ __forceinline__ float f_ricci(float x) {
    float z = x / (1.0f + x);
    float t = -z;
    float p = 0.14805913578876898f;
    p = p * t + 0.64290613877355551f;
    p = p * t + 1.0616084849547165f;
    p = p * t + 0.93524391761244940f;
    p = p * t + 0.62718906618071668f;
    p = p * t + 0.32171431660633076f;
    p = p * t + 0.32056016125642045f;
    p = p * t + 0.77373949685442023f;
    p = p * t + 0.22757881388024176f;
    p = p * t + 0.0f;
    return logf(2.0f * x + 1.0f) + p;
}

__device__ __forceinline__ float g_ricci(float x) {
    float z = x / (2.0f + x);
    float num = z * (3.5441754117462949f + z * (-7.0529131065835378f + z * (-56.532378057580381f
              + z * (279.56761105465944f + z * (-520.37554849441472f + z * (456.58245777026514f
              + z * (-155.73340457809226f)))))));
    float den = 1.0f + z * (-4.1357968834226053f + z * (-7.2984226138266743f + z * (98.656602235468327f
              + z * (-334.20436223415163f + z * (601.08633903294185f + z * (-599.58577549598340f
              + z * (277.18420330693891f + z * (-16.445022798669722f))))))));
    return num / den;
}

__device__ __forceinline__ float phi_f(float mu, float sig, float tau_ref) {
    const float tau = 0.01f;
    float xp = mu / sig;             // VR = 0
    float xm = (mu - 20.0f) / sig;   // VT = 20
    float r0;
    if (xm > 0.0f) {
        r0 = 1.0f / (f_ricci(xp) - f_ricci(xm));
    } else if (xp > 0.0f) {
        r0 = 1.0f / (f_ricci(xp) + expf(xm * xm) * g_ricci(-xm));
    } else {
        r0 = expf(-xm * xm - logf(g_ricci(-xm) - expf(xp * xp - xm * xm) * g_ricci(-xp)));
    }
    r0 = fmaxf(r0, 1e-30f);
    return 1.0f / (tau_ref + tau / r0);
}

// ---------------- setup kernels ----------------
__global__ void k_weights(const float* __restrict__ hyp, const float* __restrict__ rnd) {
    int tid = blockIdx.x * blockDim.x + threadIdx.x;
    if (tid >= NN * NN) return;
    int j = tid / NN;
    int i = tid - j * NN;                         // output layout [j][i] (coalesced write)
    int conn = (i >= NE ? 1 : 0) + 2 * (j >= NE ? 1 : 0);
    float J = hyp[conn], P = hyp[4 + conn], Wp = hyp[8 + conn];
    const float cd = 3.14159265358979323846f / 180.0f;
    float diff = fabsf(prefv(i) - prefv(j));
    float wden = 4.0f * (cd * Wp) * (cd * Wp);
    float z = expf((cosf(2.0f * cd * diff) - 1.0f) / wden);
    float x = 32.0f * (P * z - rnd[(size_t)i * NN + j]);
    float w = J / (1.0f + expf(-x));
    d_W1[tid] = w;
    d_W2[tid] = w * w;
}

__global__ void k_mean() {
    int tid = blockIdx.x * blockDim.x + threadIdx.x;
    if (tid >= NB * NN) return;
    int b = tid / NN;
    int n = tid - b * NN;
    int c = b / 12;
    int o = b - c * 12;
    const float cd = 3.14159265358979323846f / 180.0f;
    float dth = (float)o * 15.0f - prefv(n);
    const float wden = 4.0f * (cd * 30.0f) * (cd * 30.0f);
    float cg = expf((cosf(2.0f * cd * dth) - 1.0f) / wden);
    d_mean[tid] = c_contr[c] * 20.0f * cg;
}

// ---------------- step kernels ----------------
// Fused dual GEMM, f32x2 packed across NEURON PAIRS:
//   thread t owns neurons (2p, 2p+1); acc_mu[b] = (mu[2p][b], mu[2p+1][b]) etc.
//   weight LDG.64 yields (w[i],w[i+1]) pre-packed; rate broadcast stored duplicated
//   in smem so one LDS.64 feeds both the mu and s2 FMA. Zero packing MOVs.
// Grid: (3 pair blocks of 256) x (6 batch blocks of 16) x (split-K 25 of 60)
__global__ __launch_bounds__(256, 3) void k_accum(int rsel) {
    const float* __restrict__ rate = rsel ? d_rateB : d_rateA;
    const int p  = blockIdx.x * 256 + threadIdx.x;     // neuron-pair index
    const int b0 = blockIdx.y * 16;
    const int j0 = blockIdx.z * KC;
    const int pC = (p < NN / 2) ? p : (NN / 2 - 1);

    // rs[b][jj] = (rate[b0+b][j0+jj], same) -- duplicated scalar as f32x2
    __shared__ u64 rs[16][KC + 1];
    for (int idx = threadIdx.x; idx < 16 * KC; idx += 256) {
        int bl = idx / KC;
        int jj = idx - bl * KC;
        float v = rate[(b0 + bl) * NN + j0 + jj];
        rs[bl][jj] = pack2(v, v);
    }
    __syncthreads();

    u64 am[16], as[16];
#pragma unroll
    for (int b = 0; b < 16; b++) { am[b] = 0ULL; as[b] = 0ULL; }

    const u64* w1p = (const u64*)(d_W1 + (size_t)j0 * NN) + pC;   // 8B-aligned (2p even)
    const u64* w2p = (const u64*)(d_W2 + (size_t)j0 * NN) + pC;
    const int strd = NN / 2;   // u64 stride per j

    // software pipeline: DEPTH j-rows of (w-pair, w2-pair) in flight
    u64 w1buf[DEPTH], w2buf[DEPTH];
#pragma unroll
    for (int u = 0; u < DEPTH; u++) {
        w1buf[u] = w1p[(size_t)u * strd];
        w2buf[u] = w2p[(size_t)u * strd];
    }
    w1p += (size_t)DEPTH * strd;
    w2p += (size_t)DEPTH * strd;

    for (int base = 0; base < KC; base += DEPTH) {     // KC = 60 = 20 * DEPTH
        u64 c1[DEPTH], c2[DEPTH];
#pragma unroll
        for (int u = 0; u < DEPTH; u++) { c1[u] = w1buf[u]; c2[u] = w2buf[u]; }
        if (base + DEPTH < KC) {
#pragma unroll
            for (int u = 0; u < DEPTH; u++) {
                w1buf[u] = w1p[(size_t)u * strd];
                w2buf[u] = w2p[(size_t)u * strd];
            }
            w1p += (size_t)DEPTH * strd;
            w2p += (size_t)DEPTH * strd;
        }
#pragma unroll
        for (int u = 0; u < DEPTH; u++) {
#pragma unroll
            for (int b = 0; b < 16; b++) {
                u64 r = rs[b][base + u];    // uniform LDS.64 broadcast, reused x2
                fma2(am[b], r, c1[u]);      // (mu_2p, mu_2p+1)
                fma2(as[b], r, c2[u]);      // (s2_2p, s2_2p+1)
            }
        }
    }

    if (p < NN / 2) {
        const int kb = blockIdx.z * NB;
#pragma unroll
        for (int b = 0; b < 16; b++) {
            *(u64*)(d_pmu + (size_t)(kb + b0 + b) * NN + 2 * p) = am[b];  // STG.64
            *(u64*)(d_ps2 + (size_t)(kb + b0 + b) * NN + 2 * p) = as[b];
        }
    }
}

// Reduce split-K partials, apply phi, Euler update.
__global__ void k_update(int rsel_in, int rsel_out, int first) {
    int tid = blockIdx.x * blockDim.x + threadIdx.x;
    if (tid >= NB * NN) return;
    int b = tid / NN;
    int i = tid - b * NN;

    float ms = 0.0f, ss = 0.0f, rold = 0.0f;
    if (!first) {
        const float* rin = rsel_in ? d_rateB : d_rateA;
#pragma unroll
        for (int k = 0; k < KSPLIT; k++) {
            ms += d_pmu[(size_t)(k * NB + b) * NN + i];
            ss += d_ps2[(size_t)(k * NB + b) * NN + i];
        }
        rold = rin[tid];
    }
    float mu  = 0.01f * ms + d_mean[tid];
    float sig = sqrtf(0.01f * ss + 25.0f);     // SIG_EXT^2 = 25
    float tr = (i < NE) ? 0.005f : 0.001f;
    float aT = (i < NE) ? 0.1f : 0.2f;         // DT * T_inv
    float ph = phi_f(mu, sig, tr);
    float* rout = rsel_out ? d_rateB : d_rateA;
    rout[tid] = rold + aT * (ph - rold);
}

// out[n, c, o] = rate[c*12+o, n]
__global__ void k_out(int rsel, float* __restrict__ out) {
    int tid = blockIdx.x * blockDim.x + threadIdx.x;
    if (tid >= NB * NN) return;
    int n = tid / NB;
    int b = tid - n * NB;
    const float* r = rsel ? d_rateB : d_rateA;
    out[tid] = r[b * NN + n];
}

// ---------------- launch ----------------
extern "C" void kernel_launch(void* const* d_in, const int* in_sizes, int n_in,
                              void* d_out, int out_size) {
    const float* hyp = (const float*)d_in[0];
    const float* rnd = (const float*)d_in[1];
    float* out = (float*)d_out;

    k_weights<<<(NN * NN + 255) / 256, 256>>>(hyp, rnd);
    k_mean<<<(NB * NN + 255) / 256, 256>>>();

    const int UB = (NB * NN + 255) / 256;
    // step 1: rate starts at zero -> mu = mean, sig = 5; write into B
    k_update<<<UB, 256>>>(0, 1, 1);
    int cur = 1;
    for (int s = 1; s < NSTEPS; s++) {
        k_accum<<<dim3(3, 6, KSPLIT), 256>>>(cur);
        k_update<<<UB, 256>>>(cur, cur ^ 1, 0);
        cur ^= 1;
    }
    k_out<<<(NB * NN + 255) / 256, 256>>>(cur, out);
}

// round 4
// speedup vs baseline: 2.1488x; 2.1488x over previous
#include <cuda_runtime.h>
#include <math.h>

#define NN 1500
#define NE 1200
#define NB 96
#define KC 100
#define KSPLIT 15
#define NSTEPS 60
#define DEPTH 4     // prefetch depth; KC = 100 = 25 * 4

typedef unsigned long long u64;

// ---------------- static device buffers (no allocations allowed) ----------------
// 8 padding rows so the software pipeline may prefetch past j=1499 harmlessly.
__device__ float2 d_WW[(size_t)(NN + 8) * NN];    // [j][i] = (W[i][j], W[i][j]^2)  18MB
__device__ float  d_mean[NB * NN];                // [b][i]
__device__ float  d_rateA[NB * NN];               // ping
__device__ float  d_rateB[NB * NN];               // pong
__device__ float  d_pmu[KSPLIT * NB * NN];        // split-K partials of rate@W^T
__device__ float  d_ps2[KSPLIT * NB * NN];        // split-K partials of rate@(W^2)^T

__constant__ float c_contr[8] = {0.0f, 0.0432773f, 0.103411f, 0.186966f,
                                 0.303066f, 0.464386f, 0.68854f, 1.0f};

// ---------------- helpers ----------------
__device__ __forceinline__ float prefv(int n) {
    const float se = 179.99f / 1200.0f;
    const float si = 179.99f / 300.0f;
    return (n < NE) ? (float)n * se : (float)(n - NE) * si;
}

__device__ __forceinline__ u64 pack2(float x, float y) {
    u64 r;
    asm("mov.b64 %0, {%1,%2};" : "=l"(r) : "f"(x), "f"(y));
    return r;
}
__device__ __forceinline__ void unpack2(u64 v, float& x, float& y) {
    asm("mov.b64 {%0,%1}, %2;" : "=f"(x), "=f"(y) : "l"(v));
}
// packed dual FMA: d.lo += a.lo*b.lo ; d.hi += a.hi*b.hi   (FFMA2, sm_103a)
__device__ __forceinline__ void fma2(u64& d, u64 a, u64 b) {
    asm("fma.rn.f32x2 %0, %1, %2, %0;" : "+l"(d) : "l"(a), "l"(b));
}

// ---------------- Ricciardi transfer ----------------
__device__ __forceinline__ float f_ricci(float x) {
    float z = x / (1.0f + x);
    float t = -z;
    float p = 0.14805913578876898f;
    p = p * t + 0.64290613877355551f;
    p = p * t + 1.0616084849547165f;
    p = p * t + 0.93524391761244940f;
    p = p * t + 0.62718906618071668f;
    p = p * t + 0.32171431660633076f;
    p = p * t + 0.32056016125642045f;
    p = p * t + 0.77373949685442023f;
    p = p * t + 0.22757881388024176f;
    p = p * t + 0.0f;
    return logf(2.0f * x + 1.0f) + p;
}

__device__ __forceinline__ float g_ricci(float x) {
    float z = x / (2.0f + x);
    float num = z * (3.5441754117462949f + z * (-7.0529131065835378f + z * (-56.532378057580381f
              + z * (279.56761105465944f + z * (-520.37554849441472f + z * (456.58245777026514f
              + z * (-155.73340457809226f)))))));
    float den = 1.0f + z * (-4.1357968834226053f + z * (-7.2984226138266743f + z * (98.656602235468327f
              + z * (-334.20436223415163f + z * (601.08633903294185f + z * (-599.58577549598340f
              + z * (277.18420330693891f + z * (-16.445022798669722f))))))));
    return num / den;
}

__device__ __forceinline__ float phi_f(float mu, float sig, float tau_ref) {
    const float tau = 0.01f;
    float xp = mu / sig;             // VR = 0
    float xm = (mu - 20.0f) / sig;   // VT = 20
    float r0;
    if (xm > 0.0f) {
        r0 = 1.0f / (f_ricci(xp) - f_ricci(xm));
    } else if (xp > 0.0f) {
        r0 = 1.0f / (f_ricci(xp) + expf(xm * xm) * g_ricci(-xm));
    } else {
        r0 = expf(-xm * xm - logf(g_ricci(-xm) - expf(xp * xp - xm * xm) * g_ricci(-xp)));
    }
    r0 = fmaxf(r0, 1e-30f);
    return 1.0f / (tau_ref + tau / r0);
}

// ---------------- setup kernels ----------------
__global__ void k_weights(const float* __restrict__ hyp, const float* __restrict__ rnd) {
    int tid = blockIdx.x * blockDim.x + threadIdx.x;
    if (tid >= NN * NN) return;
    int j = tid / NN;
    int i = tid - j * NN;                         // output layout [j][i] (coalesced write)
    int conn = (i >= NE ? 1 : 0) + 2 * (j >= NE ? 1 : 0);
    float J = hyp[conn], P = hyp[4 + conn], Wp = hyp[8 + conn];
    const float cd = 3.14159265358979323846f / 180.0f;
    float diff = fabsf(prefv(i) - prefv(j));
    float wden = 4.0f * (cd * Wp) * (cd * Wp);
    float z = expf((cosf(2.0f * cd * diff) - 1.0f) / wden);
    float x = 32.0f * (P * z - rnd[(size_t)i * NN + j]);
    float w = J / (1.0f + expf(-x));
    d_WW[tid] = make_float2(w, w * w);
}

__global__ void k_mean() {
    int tid = blockIdx.x * blockDim.x + threadIdx.x;
    if (tid >= NB * NN) return;
    int b = tid / NN;
    int n = tid - b * NN;
    int c = b / 12;
    int o = b - c * 12;
    const float cd = 3.14159265358979323846f / 180.0f;
    float dth = (float)o * 15.0f - prefv(n);
    const float wden = 4.0f * (cd * 30.0f) * (cd * 30.0f);
    float cg = expf((cosf(2.0f * cd * dth) - 1.0f) / wden);
    d_mean[tid] = c_contr[c] * 20.0f * cg;
}

// ---------------- step kernels ----------------
// Fused dual GEMM: mu_part[b,i] = sum_j rate[b,j]*W[i,j]; s2_part likewise with W^2.
// Grid: (6 neuron blocks of 256) x (6 batch blocks of 16) x (split-K 15 of 100)
// 540 CTAs -> 4 CTAs/SM on most SMs; DEPTH=4 in-place prefetch pipeline.
__global__ __launch_bounds__(256, 4) void k_accum(int rsel) {
    const float* __restrict__ rate = rsel ? d_rateB : d_rateA;
    const int i  = blockIdx.x * 256 + threadIdx.x;
    const int b0 = blockIdx.y * 16;
    const int j0 = blockIdx.z * KC;
    const int iC = (i < NN) ? i : (NN - 1);

    // rate tile as batch-pair-packed f32x2: rs[bp][jj] = (rate[b0+2bp][j], rate[b0+2bp+1][j])
    __shared__ u64 rs[8][KC + 1];
    float* rsf = (float*)rs;
    for (int idx = threadIdx.x; idx < 16 * KC; idx += 256) {
        int bl = idx / KC;
        int jj = idx - bl * KC;
        float v = rate[(b0 + bl) * NN + j0 + jj];
        rsf[(((bl >> 1) * (KC + 1)) + jj) * 2 + (bl & 1)] = v;
    }
    __syncthreads();

    u64 am[8], as[8];
#pragma unroll
    for (int p = 0; p < 8; p++) { am[p] = 0ULL; as[p] = 0ULL; }

    const float2* wp = d_WW + (size_t)j0 * NN + iC;

    // in-place software pipeline: DEPTH weight loads in flight, no shadow copies
    float2 wbuf[DEPTH];
#pragma unroll
    for (int u = 0; u < DEPTH; u++) wbuf[u] = wp[(size_t)u * NN];
    wp += (size_t)DEPTH * NN;

    for (int base = 0; base < KC; base += DEPTH) {     // KC = 100 = 25 * DEPTH
#pragma unroll
        for (int u = 0; u < DEPTH; u++) {
            u64 wa = pack2(wbuf[u].x, wbuf[u].x);
            u64 wb = pack2(wbuf[u].y, wbuf[u].y);
            wbuf[u] = *wp;                 // refill slot immediately (pad rows make OOB safe)
            wp += NN;
#pragma unroll
            for (int p = 0; p < 8; p++) {
                u64 r = rs[p][base + u];   // broadcast LDS.64
                fma2(am[p], r, wa);        // mu accum for batch pair
                fma2(as[p], r, wb);        // sigma^2 accum for batch pair
            }
        }
    }

    if (i < NN) {
        const int kb = blockIdx.z * NB;
#pragma unroll
        for (int p = 0; p < 8; p++) {
            float lo, hi;
            unpack2(am[p], lo, hi);
            d_pmu[(size_t)(kb + b0 + 2 * p) * NN + i]     = lo;
            d_pmu[(size_t)(kb + b0 + 2 * p + 1) * NN + i] = hi;
            unpack2(as[p], lo, hi);
            d_ps2[(size_t)(kb + b0 + 2 * p) * NN + i]     = lo;
            d_ps2[(size_t)(kb + b0 + 2 * p + 1) * NN + i] = hi;
        }
    }
}

// Reduce split-K partials, apply phi, Euler update.
__global__ void k_update(int rsel_in, int rsel_out, int first) {
    int tid = blockIdx.x * blockDim.x + threadIdx.x;
    if (tid >= NB * NN) return;
    int b = tid / NN;
    int i = tid - b * NN;

    float ms = 0.0f, ss = 0.0f, rold = 0.0f;
    if (!first) {
        const float* rin = rsel_in ? d_rateB : d_rateA;
#pragma unroll
        for (int k = 0; k < KSPLIT; k++) {
            ms += d_pmu[(size_t)(k * NB + b) * NN + i];
            ss += d_ps2[(size_t)(k * NB + b) * NN + i];
        }
        rold = rin[tid];
    }
    float mu  = 0.01f * ms + d_mean[tid];
    float sig = sqrtf(0.01f * ss + 25.0f);     // SIG_EXT^2 = 25
    float tr = (i < NE) ? 0.005f : 0.001f;
    float aT = (i < NE) ? 0.1f : 0.2f;         // DT * T_inv
    float ph = phi_f(mu, sig, tr);
    float* rout = rsel_out ? d_rateB : d_rateA;
    rout[tid] = rold + aT * (ph - rold);
}

// out[n, c, o] = rate[c*12+o, n]
__global__ void k_out(int rsel, float* __restrict__ out) {
    int tid = blockIdx.x * blockDim.x + threadIdx.x;
    if (tid >= NB * NN) return;
    int n = tid / NB;
    int b = tid - n * NB;
    const float* r = rsel ? d_rateB : d_rateA;
    out[tid] = r[b * NN + n];
}

// ---------------- launch ----------------
extern "C" void kernel_launch(void* const* d_in, const int* in_sizes, int n_in,
                              void* d_out, int out_size) {
    const float* hyp = (const float*)d_in[0];
    const float* rnd = (const float*)d_in[1];
    float* out = (float*)d_out;

    k_weights<<<(NN * NN + 255) / 256, 256>>>(hyp, rnd);
    k_mean<<<(NB * NN + 255) / 256, 256>>>();

    const int UB = (NB * NN + 255) / 256;
    // step 1: rate starts at zero -> mu = mean, sig = 5; write into B
    k_update<<<UB, 256>>>(0, 1, 1);
    int cur = 1;
    for (int s = 1; s < NSTEPS; s++) {
        k_accum<<<dim3(6, 6, KSPLIT), 256>>>(cur);
        k_update<<<UB, 256>>>(cur, cur ^ 1, 0);
        cur ^= 1;
    }
    k_out<<<(NB * NN + 255) / 256, 256>>>(cur, out);
}

// round 6
// speedup vs baseline: 4.8483x; 2.2562x over previous
#include <cuda_runtime.h>
#include <cuda_bf16.h>
#include <math.h>
#include <cstdint>

#define NN 1500
#define NE 1200
#define NB 96
#define NSEG 1536
#define KTOT 4608          // 3*NSEG
#define NTOT 3072          // 2*NSEG
#define MM 128             // padded batch
#define NT 128             // N-tile per CTA
#define NTILES 24          // NTOT/NT
#define KSP 12             // split-K
#define KCTA 384           // KTOT/KSP
#define KCH 64             // bf16 K per smem chunk
#define CH 6               // KCTA/KCH
#define NSTEPS 60

// padded smem row: 64 bf16 data + 8 pad = 72 bf16 = 144 bytes (conflict-free frags)
#define ROWB 144
#define TILEB (128 * ROWB)          // 18432 B per operand chunk
#define SMEM_TOTAL (4 * TILEB)      // A0 B0 A1 B1 = 73728 B

typedef unsigned int u32;
typedef unsigned long long u64;

// ---------------- static device buffers ----------------
__device__ __nv_bfloat16 d_A[(size_t)MM * KTOT];        // [b][k]  1.18MB
__device__ __nv_bfloat16 d_B[(size_t)NTOT * KTOT];      // [n][k]  28.3MB
__device__ float d_part[(size_t)KSP * NB * NTOT];       // 14.2MB split-K partials
__device__ float d_rate[NB * NN];
__device__ float d_mean[NB * NN];

__constant__ float c_contr[8] = {0.0f, 0.0432773f, 0.103411f, 0.186966f,
                                 0.303066f, 0.464386f, 0.68854f, 1.0f};

// ---------------- PTX helpers (base ISA only) ----------------
__device__ __forceinline__ u32 smem_u32(const void* p) {
    u32 a;
    asm("{ .reg .u64 t; cvta.to.shared.u64 t, %1; cvt.u32.u64 %0, t; }" : "=r"(a) : "l"(p));
    return a;
}
__device__ __forceinline__ u32 lds32(u32 addr) {
    u32 v;
    asm volatile("ld.shared.b32 %0, [%1];" : "=r"(v) : "r"(addr));
    return v;
}
__device__ __forceinline__ void cpasync16(u32 saddr, const void* gaddr) {
    asm volatile("cp.async.cg.shared.global [%0], [%1], 16;" :: "r"(saddr), "l"(gaddr));
}
__device__ __forceinline__ void mma16816(float* c, u32 a0, u32 a1, u32 a2, u32 a3,
                                         u32 b0, u32 b1) {
    asm volatile("mma.sync.aligned.m16n8k16.row.col.f32.bf16.bf16.f32 "
                 "{%0,%1,%2,%3}, {%4,%5,%6,%7}, {%8,%9}, {%0,%1,%2,%3};"
                 : "+f"(c[0]), "+f"(c[1]), "+f"(c[2]), "+f"(c[3])
                 : "r"(a0), "r"(a1), "r"(a2), "r"(a3), "r"(b0), "r"(b1));
}

// ---------------- math helpers ----------------
__device__ __forceinline__ float prefv(int n) {
    const float se = 179.99f / 1200.0f;
    const float si = 179.99f / 300.0f;
    return (n < NE) ? (float)n * se : (float)(n - NE) * si;
}
__device__ __forceinline__ float f_ricci(float x) {
    float z = x / (1.0f + x);
    float t = -z;
    float p = 0.14805913578876898f;
    p = p * t + 0.64290613877355551f;
    p = p * t + 1.0616084849547165f;
    p = p * t + 0.93524391761244940f;
    p = p * t + 0.62718906618071668f;
    p = p * t + 0.32171431660633076f;
    p = p * t + 0.32056016125642045f;
    p = p * t + 0.77373949685442023f;
    p = p * t + 0.22757881388024176f;
    p = p * t + 0.0f;
    return logf(2.0f * x + 1.0f) + p;
}
__device__ __forceinline__ float g_ricci(float x) {
    float z = x / (2.0f + x);
    float num = z * (3.5441754117462949f + z * (-7.0529131065835378f + z * (-56.532378057580381f
              + z * (279.56761105465944f + z * (-520.37554849441472f + z * (456.58245777026514f
              + z * (-155.73340457809226f)))))));
    float den = 1.0f + z * (-4.1357968834226053f + z * (-7.2984226138266743f + z * (98.656602235468327f
              + z * (-334.20436223415163f + z * (601.08633903294185f + z * (-599.58577549598340f
              + z * (277.18420330693891f + z * (-16.445022798669722f))))))));
    return num / den;
}
__device__ __forceinline__ float phi_f(float mu, float sig, float tau_ref) {
    const float tau = 0.01f;
    float xp = mu / sig;
    float xm = (mu - 20.0f) / sig;
    float r0;
    if (xm > 0.0f) {
        r0 = 1.0f / (f_ricci(xp) - f_ricci(xm));
    } else if (xp > 0.0f) {
        r0 = 1.0f / (f_ricci(xp) + expf(xm * xm) * g_ricci(-xm));
    } else {
        r0 = expf(-xm * xm - logf(g_ricci(-xm) - expf(xp * xp - xm * xm) * g_ricci(-xp)));
    }
    r0 = fmaxf(r0, 1e-30f);
    return 1.0f / (tau_ref + tau / r0);
}

// ---------------- setup kernels ----------------
// B'' row i<1536 (mu):  K segments [wh | wl | wh]
// B'' row 1536+i (s2):  K segments [w2h | w2l | w2h]
// paired with A'' segments [ah | ah | al] -> w*a ≈ wh*ah + wl*ah + wh*al
__global__ void k_weightsB(const float* __restrict__ hyp, const float* __restrict__ rnd) {
    int tid = blockIdx.x * blockDim.x + threadIdx.x;
    if (tid >= NSEG * NSEG) return;
    int i = tid / NSEG;          // output neuron (B row)
    int j = tid - i * NSEG;      // input neuron (K)
    float w = 0.0f;
    if (i < NN && j < NN) {
        int conn = (i >= NE ? 1 : 0) + 2 * (j >= NE ? 1 : 0);
        float J = hyp[conn], P = hyp[4 + conn], Wp = hyp[8 + conn];
        const float cd = 3.14159265358979323846f / 180.0f;
        float diff = fabsf(prefv(i) - prefv(j));
        float wden = 4.0f * (cd * Wp) * (cd * Wp);
        float z = expf((cosf(2.0f * cd * diff) - 1.0f) / wden);
        float x = 32.0f * (P * z - rnd[(size_t)i * NN + j]);
        w = J / (1.0f + expf(-x));
    }
    float w2 = w * w;
    __nv_bfloat16 wh = __float2bfloat16(w);
    __nv_bfloat16 wl = __float2bfloat16(w - __bfloat162float(wh));
    __nv_bfloat16 vh = __float2bfloat16(w2);
    __nv_bfloat16 vl = __float2bfloat16(w2 - __bfloat162float(vh));
    size_t r1 = (size_t)i * KTOT;
    size_t r2 = (size_t)(NSEG + i) * KTOT;
    d_B[r1 + j] = wh; d_B[r1 + NSEG + j] = wl; d_B[r1 + 2 * NSEG + j] = wh;
    d_B[r2 + j] = vh; d_B[r2 + NSEG + j] = vl; d_B[r2 + 2 * NSEG + j] = vh;
}

__global__ void k_mean() {
    int tid = blockIdx.x * blockDim.x + threadIdx.x;
    if (tid >= NB * NN) return;
    int b = tid / NN;
    int n = tid - b * NN;
    int c = b / 12;
    int o = b - c * 12;
    const float cd = 3.14159265358979323846f / 180.0f;
    float dth = (float)o * 15.0f - prefv(n);
    const float wden = 4.0f * (cd * 30.0f) * (cd * 30.0f);
    float cg = expf((cosf(2.0f * cd * dth) - 1.0f) / wden);
    d_mean[tid] = c_contr[c] * 20.0f * cg;
}

__global__ void k_zeroA() {
    int tid = blockIdx.x * blockDim.x + threadIdx.x;
    if (tid < MM * KTOT) d_A[tid] = __float2bfloat16(0.0f);
}

// ---------------- bf16 mma.sync GEMM step ----------------
// grid (24 n-tiles, 12 split-K), 256 threads.
// Per CTA: D[128,128] = A''[128, 384-slice] * B''tile^T, cp.async double-buffered.
__global__ __launch_bounds__(256, 2) void k_mma() {
    extern __shared__ char sm[];
    u32 sb = smem_u32(sm);
    const int tid = threadIdx.x, wid = tid >> 5, lane = tid & 31;
    const int n0 = blockIdx.x * NT;
    const int z = blockIdx.y;
    const int kbase = z * KCTA;

    const char* Agc = (const char*)d_A;
    const char* Bgc = (const char*)d_B;

    float acc[2][8][4];
#pragma unroll
    for (int mt = 0; mt < 2; mt++)
#pragma unroll
        for (int j = 0; j < 8; j++)
#pragma unroll
            for (int q = 0; q < 4; q++) acc[mt][j][q] = 0.0f;

    const int m_off = (wid & 3) * 32;
    const int n_off = (wid >> 2) * 64;
    const int grp = lane >> 2;          // 0..7
    const int kq = (lane & 3) * 2;      // 0,2,4,6 (halves)

    // ---- prefetch chunk 0 ----
    {
        int kg = kbase;
        u32 bufA = sb, bufB = sb + TILEB;
#pragma unroll
        for (int it = 0; it < 4; it++) {
            int u = tid + 256 * it; int row = u >> 3; int wq = u & 7;
            cpasync16(bufA + row * ROWB + wq * 16,
                      Agc + ((size_t)row * KTOT + kg + wq * 8) * 2);
        }
#pragma unroll
        for (int it = 0; it < 4; it++) {
            int u = tid + 256 * it; int row = u >> 3; int wq = u & 7;
            cpasync16(bufB + row * ROWB + wq * 16,
                      Bgc + ((size_t)(n0 + row) * KTOT + kg + wq * 8) * 2);
        }
        asm volatile("cp.async.commit_group;" ::: "memory");
    }

    for (int c = 0; c < CH; c++) {
        if (c < CH - 1) {               // prefetch next chunk into other buffer
            int kg = kbase + (c + 1) * KCH;
            u32 bufA = sb + (((c + 1) & 1) ? 2u * TILEB : 0u);
            u32 bufB = bufA + TILEB;
#pragma unroll
            for (int it = 0; it < 4; it++) {
                int u = tid + 256 * it; int row = u >> 3; int wq = u & 7;
                cpasync16(bufA + row * ROWB + wq * 16,
                          Agc + ((size_t)row * KTOT + kg + wq * 8) * 2);
            }
#pragma unroll
            for (int it = 0; it < 4; it++) {
                int u = tid + 256 * it; int row = u >> 3; int wq = u & 7;
                cpasync16(bufB + row * ROWB + wq * 16,
                          Bgc + ((size_t)(n0 + row) * KTOT + kg + wq * 8) * 2);
            }
            asm volatile("cp.async.commit_group;" ::: "memory");
            asm volatile("cp.async.wait_group 1;" ::: "memory");
        } else {
            asm volatile("cp.async.wait_group 0;" ::: "memory");
        }
        __syncthreads();

        u32 bufA = sb + ((c & 1) ? 2u * TILEB : 0u);
        u32 bufB = bufA + TILEB;

#pragma unroll
        for (int ks = 0; ks < 4; ks++) {
            int kk = ks * 16 + kq;                       // half index within chunk
            u32 aAddr0 = bufA + (m_off + grp) * ROWB + kk * 2;
            u32 aAddr1 = aAddr0 + 16 * ROWB;             // second m16 tile
            u32 a0 = lds32(aAddr0);
            u32 a1 = lds32(aAddr0 + 8 * ROWB);
            u32 a2 = lds32(aAddr0 + 16);
            u32 a3 = lds32(aAddr0 + 8 * ROWB + 16);
            u32 a4 = lds32(aAddr1);
            u32 a5 = lds32(aAddr1 + 8 * ROWB);
            u32 a6 = lds32(aAddr1 + 16);
            u32 a7 = lds32(aAddr1 + 8 * ROWB + 16);
#pragma unroll
            for (int j = 0; j < 8; j++) {
                u32 bAddr = bufB + (n_off + j * 8 + grp) * ROWB + kk * 2;
                u32 b0 = lds32(bAddr);
                u32 b1 = lds32(bAddr + 16);
                mma16816(acc[0][j], a0, a1, a2, a3, b0, b1);
                mma16816(acc[1][j], a4, a5, a6, a7, b0, b1);
            }
        }
        __syncthreads();
    }

    // ---- epilogue: write split-K partials (only real batches b<96) ----
#pragma unroll
    for (int mt = 0; mt < 2; mt++) {
        int br0 = m_off + mt * 16 + grp;
        int br1 = br0 + 8;
#pragma unroll
        for (int j = 0; j < 8; j++) {
            int col = n0 + n_off + j * 8 + (lane & 3) * 2;
            if (br0 < NB)
                *(float2*)(d_part + ((size_t)z * NB + br0) * NTOT + col) =
                    make_float2(acc[mt][j][0], acc[mt][j][1]);
            if (br1 < NB)
                *(float2*)(d_part + ((size_t)z * NB + br1) * NTOT + col) =
                    make_float2(acc[mt][j][2], acc[mt][j][3]);
        }
    }
}

// ---------------- reduce + phi + Euler update + A'' split write ----------------
__global__ void k_update(int first) {
    int tid = blockIdx.x * blockDim.x + threadIdx.x;
    if (tid >= NB * NN) return;
    int b = tid / NN;
    int i = tid - b * NN;

    float ms = 0.0f, ss = 0.0f, rold = 0.0f;
    if (!first) {
        rold = d_rate[tid];
#pragma unroll
        for (int z = 0; z < KSP; z++) {
            ms += d_part[((size_t)z * NB + b) * NTOT + i];
            ss += d_part[((size_t)z * NB + b) * NTOT + NSEG + i];
        }
    }
    float mu  = 0.01f * ms + d_mean[tid];
    float sig = sqrtf(0.01f * ss + 25.0f);
    float tr = (i < NE) ? 0.005f : 0.001f;
    float aT = (i < NE) ? 0.1f : 0.2f;
    float ph = phi_f(mu, sig, tr);
    float rnew = rold + aT * (ph - rold);
    d_rate[tid] = rnew;
    // A'' split: segments [ah | ah | al] matching B'' [wh | wl | wh]
    __nv_bfloat16 ah = __float2bfloat16(rnew);
    __nv_bfloat16 al = __float2bfloat16(rnew - __bfloat162float(ah));
    size_t ar = (size_t)b * KTOT;
    d_A[ar + i] = ah;
    d_A[ar + NSEG + i] = ah;
    d_A[ar + 2 * NSEG + i] = al;
}

// out[n, c, o] = rate[c*12+o, n]
__global__ void k_out(float* __restrict__ out) {
    int tid = blockIdx.x * blockDim.x + threadIdx.x;
    if (tid >= NB * NN) return;
    int n = tid / NB;
    int b = tid - n * NB;
    out[tid] = d_rate[b * NN + n];
}

// ---------------- launch ----------------
extern "C" void kernel_launch(void* const* d_in, const int* in_sizes, int n_in,
                              void* d_out, int out_size) {
    const float* hyp = (const float*)d_in[0];
    const float* rnd = (const float*)d_in[1];
    float* out = (float*)d_out;

    cudaFuncSetAttribute(k_mma, cudaFuncAttributeMaxDynamicSharedMemorySize, SMEM_TOTAL);

    k_weightsB<<<(NSEG * NSEG + 255) / 256, 256>>>(hyp, rnd);
    k_mean<<<(NB * NN + 255) / 256, 256>>>();
    k_zeroA<<<(MM * KTOT + 255) / 256, 256>>>();

    const int UB = (NB * NN + 255) / 256;
    k_update<<<UB, 256>>>(1);                     // step 1: rate=0 -> mu=mean, sig=5
    for (int s = 1; s < NSTEPS; s++) {
        k_mma<<<dim3(NTILES, KSP), 256, SMEM_TOTAL>>>();
        k_update<<<UB, 256>>>(0);
    }
    k_out<<<(NB * NN + 255) / 256, 256>>>(out);
}

// round 7
// speedup vs baseline: 5.2676x; 1.0865x over previous
#include <cuda_runtime.h>
#include <cuda_bf16.h>
#include <math.h>
#include <cstdint>

#define NN 1500
#define NE 1200
#define NB 96
#define NSEG 1536
#define KTOT 4608          // 3*NSEG
#define NTOT 3072          // 2*NSEG (interleaved: row 2n=mu(n), 2n+1=s2(n))
#define MM 96              // batch rows (6 x m16)
#define NT 128             // N-tile per CTA
#define NTILES 24          // NTOT/NT
#define KSP 12             // split-K
#define KCTA 384           // KTOT/KSP
#define KCH 64             // bf16 K per smem chunk
#define CH 6               // KCTA/KCH
#define NSTEPS 60
#define NPAIR 750          // NN/2
#define UTOT (NB * NPAIR)  // update threads

// padded smem row: 64 bf16 data + 8 pad = 72 bf16 = 144 bytes (conflict-free frags)
#define ROWB 144
#define TILEA (MM * ROWB)            // 13824
#define TILEB_ (NT * ROWB)           // 18432
#define BUFSZ (TILEA + TILEB_)       // 32256
#define SMEM_TOTAL (2 * BUFSZ)       // 64512

typedef unsigned int u32;
typedef unsigned long long u64;

// ---------------- static device buffers ----------------
__device__ __align__(16) __nv_bfloat16 d_A[(size_t)MM * KTOT];     // [b][k]
__device__ __align__(16) __nv_bfloat16 d_B[(size_t)NTOT * KTOT];   // [r][k] 28.3MB
__device__ __align__(16) float d_part[(size_t)KSP * NB * NTOT];    // 14.2MB
__device__ __align__(16) float d_rate[NB * NN];
__device__ __align__(16) float d_mean[NB * NN];

__constant__ float c_contr[8] = {0.0f, 0.0432773f, 0.103411f, 0.186966f,
                                 0.303066f, 0.464386f, 0.68854f, 1.0f};

// ---------------- PTX helpers (base ISA only) ----------------
__device__ __forceinline__ u32 smem_u32(const void* p) {
    u32 a;
    asm("{ .reg .u64 t; cvta.to.shared.u64 t, %1; cvt.u32.u64 %0, t; }" : "=r"(a) : "l"(p));
    return a;
}
__device__ __forceinline__ u32 lds32(u32 addr) {
    u32 v;
    asm volatile("ld.shared.b32 %0, [%1];" : "=r"(v) : "r"(addr));
    return v;
}
__device__ __forceinline__ void cpasync16(u32 saddr, const void* gaddr) {
    asm volatile("cp.async.cg.shared.global [%0], [%1], 16;" :: "r"(saddr), "l"(gaddr));
}
__device__ __forceinline__ void mma16816(float* c, u32 a0, u32 a1, u32 a2, u32 a3,
                                         u32 b0, u32 b1) {
    asm volatile("mma.sync.aligned.m16n8k16.row.col.f32.bf16.bf16.f32 "
                 "{%0,%1,%2,%3}, {%4,%5,%6,%7}, {%8,%9}, {%0,%1,%2,%3};"
                 : "+f"(c[0]), "+f"(c[1]), "+f"(c[2]), "+f"(c[3])
                 : "r"(a0), "r"(a1), "r"(a2), "r"(a3), "r"(b0), "r"(b1));
}

// ---------------- math helpers ----------------
__device__ __forceinline__ float prefv(int n) {
    const float se = 179.99f / 1200.0f;
    const float si = 179.99f / 300.0f;
    return (n < NE) ? (float)n * se : (float)(n - NE) * si;
}
__device__ __forceinline__ float f_ricci(float x) {
    float z = x / (1.0f + x);
    float t = -z;
    float p = 0.14805913578876898f;
    p = p * t + 0.64290613877355551f;
    p = p * t + 1.0616084849547165f;
    p = p * t + 0.93524391761244940f;
    p = p * t + 0.62718906618071668f;
    p = p * t + 0.32171431660633076f;
    p = p * t + 0.32056016125642045f;
    p = p * t + 0.77373949685442023f;
    p = p * t + 0.22757881388024176f;
    p = p * t + 0.0f;
    return logf(2.0f * x + 1.0f) + p;
}
__device__ __forceinline__ float g_ricci(float x) {
    float z = x / (2.0f + x);
    float num = z * (3.5441754117462949f + z * (-7.0529131065835378f + z * (-56.532378057580381f
              + z * (279.56761105465944f + z * (-520.37554849441472f + z * (456.58245777026514f
              + z * (-155.73340457809226f)))))));
    float den = 1.0f + z * (-4.1357968834226053f + z * (-7.2984226138266743f + z * (98.656602235468327f
              + z * (-334.20436223415163f + z * (601.08633903294185f + z * (-599.58577549598340f
              + z * (277.18420330693891f + z * (-16.445022798669722f))))))));
    return num / den;
}
__device__ __forceinline__ float phi_f(float mu, float sig, float tau_ref) {
    const float tau = 0.01f;
    float xp = mu / sig;
    float xm = (mu - 20.0f) / sig;
    float r0;
    if (xm > 0.0f) {
        r0 = 1.0f / (f_ricci(xp) - f_ricci(xm));
    } else if (xp > 0.0f) {
        r0 = 1.0f / (f_ricci(xp) + expf(xm * xm) * g_ricci(-xm));
    } else {
        r0 = expf(-xm * xm - logf(g_ricci(-xm) - expf(xp * xp - xm * xm) * g_ricci(-xp)));
    }
    r0 = fmaxf(r0, 1e-30f);
    return 1.0f / (tau_ref + tau / r0);
}

// ---------------- setup kernels ----------------
// B'' row 2i   (mu neuron i): K segments [wh  | wl  | wh ]
// B'' row 2i+1 (s2 neuron i): K segments [w2h | w2l | w2h]
// paired with A'' segments [ah | ah | al] -> w*a ≈ wh*ah + wl*ah + wh*al
__global__ void k_weightsB(const float* __restrict__ hyp, const float* __restrict__ rnd) {
    int tid = blockIdx.x * blockDim.x + threadIdx.x;
    if (tid >= NSEG * NSEG) return;
    int i = tid / NSEG;          // output neuron
    int j = tid - i * NSEG;      // input neuron (K)
    float w = 0.0f;
    if (i < NN && j < NN) {
        int conn = (i >= NE ? 1 : 0) + 2 * (j >= NE ? 1 : 0);
        float J = hyp[conn], P = hyp[4 + conn], Wp = hyp[8 + conn];
        const float cd = 3.14159265358979323846f / 180.0f;
        float diff = fabsf(prefv(i) - prefv(j));
        float wden = 4.0f * (cd * Wp) * (cd * Wp);
        float z = expf((cosf(2.0f * cd * diff) - 1.0f) / wden);
        float x = 32.0f * (P * z - rnd[(size_t)i * NN + j]);
        w = J / (1.0f + expf(-x));
    }
    float w2 = w * w;
    __nv_bfloat16 wh = __float2bfloat16(w);
    __nv_bfloat16 wl = __float2bfloat16(w - __bfloat162float(wh));
    __nv_bfloat16 vh = __float2bfloat16(w2);
    __nv_bfloat16 vl = __float2bfloat16(w2 - __bfloat162float(vh));
    size_t r1 = (size_t)(2 * i) * KTOT;
    size_t r2 = (size_t)(2 * i + 1) * KTOT;
    d_B[r1 + j] = wh; d_B[r1 + NSEG + j] = wl; d_B[r1 + 2 * NSEG + j] = wh;
    d_B[r2 + j] = vh; d_B[r2 + NSEG + j] = vl; d_B[r2 + 2 * NSEG + j] = vh;
}

__global__ void k_mean() {
    int tid = blockIdx.x * blockDim.x + threadIdx.x;
    if (tid >= NB * NN) return;
    int b = tid / NN;
    int n = tid - b * NN;
    int c = b / 12;
    int o = b - c * 12;
    const float cd = 3.14159265358979323846f / 180.0f;
    float dth = (float)o * 15.0f - prefv(n);
    const float wden = 4.0f * (cd * 30.0f) * (cd * 30.0f);
    float cg = expf((cosf(2.0f * cd * dth) - 1.0f) / wden);
    d_mean[tid] = c_contr[c] * 20.0f * cg;
}

__global__ void k_zeroA() {
    int tid = blockIdx.x * blockDim.x + threadIdx.x;
    if (tid < MM * KTOT) d_A[tid] = __float2bfloat16(0.0f);
}

// ---------------- bf16 mma.sync GEMM step ----------------
// grid (24 n-tiles, 12 split-K), 256 threads.
// Per CTA: D[96,128] = A''[96, 384-slice] * B''tile^T, cp.async double-buffered.
// Warp layout 2(m)x4(n); warp tile 48x32 = 3 m-frags x 4 n-frags.
__global__ __launch_bounds__(256, 2) void k_mma() {
    extern __shared__ char sm[];
    u32 sb = smem_u32(sm);
    const int tid = threadIdx.x, wid = tid >> 5, lane = tid & 31;
    const int n0 = blockIdx.x * NT;
    const int z = blockIdx.y;
    const int kbase = z * KCTA;

    const char* Agc = (const char*)d_A;
    const char* Bgc = (const char*)d_B;

    float acc[3][4][4];
#pragma unroll
    for (int mt = 0; mt < 3; mt++)
#pragma unroll
        for (int j = 0; j < 4; j++)
#pragma unroll
            for (int q = 0; q < 4; q++) acc[mt][j][q] = 0.0f;

    const int m_w = (wid & 1) * 48;
    const int n_off = (wid >> 1) * 32;
    const int grp = lane >> 2;          // 0..7
    const int kq = (lane & 3) * 2;      // 0,2,4,6 (bf16 halves)

    // ---- prefetch chunk 0 ----
    {
        int kg = kbase;
        u32 bufA = sb, bufB = sb + TILEA;
#pragma unroll
        for (int it = 0; it < 3; it++) {         // A: 96 rows x 8 quads = 768
            int u = tid + 256 * it; int row = u >> 3; int wq = u & 7;
            cpasync16(bufA + row * ROWB + wq * 16,
                      Agc + ((size_t)row * KTOT + kg + wq * 8) * 2);
        }
#pragma unroll
        for (int it = 0; it < 4; it++) {         // B: 128 rows x 8 quads = 1024
            int u = tid + 256 * it; int row = u >> 3; int wq = u & 7;
            cpasync16(bufB + row * ROWB + wq * 16,
                      Bgc + ((size_t)(n0 + row) * KTOT + kg + wq * 8) * 2);
        }
        asm volatile("cp.async.commit_group;" ::: "memory");
    }

    for (int c = 0; c < CH; c++) {
        if (c < CH - 1) {               // prefetch next chunk into other buffer
            int kg = kbase + (c + 1) * KCH;
            u32 bufA = sb + (((c + 1) & 1) ? (u32)BUFSZ : 0u);
            u32 bufB = bufA + TILEA;
#pragma unroll
            for (int it = 0; it < 3; it++) {
                int u = tid + 256 * it; int row = u >> 3; int wq = u & 7;
                cpasync16(bufA + row * ROWB + wq * 16,
                          Agc + ((size_t)row * KTOT + kg + wq * 8) * 2);
            }
#pragma unroll
            for (int it = 0; it < 4; it++) {
                int u = tid + 256 * it; int row = u >> 3; int wq = u & 7;
                cpasync16(bufB + row * ROWB + wq * 16,
                          Bgc + ((size_t)(n0 + row) * KTOT + kg + wq * 8) * 2);
            }
            asm volatile("cp.async.commit_group;" ::: "memory");
            asm volatile("cp.async.wait_group 1;" ::: "memory");
        } else {
            asm volatile("cp.async.wait_group 0;" ::: "memory");
        }
        __syncthreads();

        u32 bufA = sb + ((c & 1) ? (u32)BUFSZ : 0u);
        u32 bufB = bufA + TILEA;

#pragma unroll
        for (int ks = 0; ks < 4; ks++) {
            int kk = ks * 16 + kq;
            u32 a[3][4];
#pragma unroll
            for (int mt = 0; mt < 3; mt++) {
                u32 aAddr = bufA + (m_w + mt * 16 + grp) * ROWB + kk * 2;
                a[mt][0] = lds32(aAddr);
                a[mt][1] = lds32(aAddr + 8 * ROWB);
                a[mt][2] = lds32(aAddr + 16);
                a[mt][3] = lds32(aAddr + 8 * ROWB + 16);
            }
#pragma unroll
            for (int j = 0; j < 4; j++) {
                u32 bAddr = bufB + (n_off + j * 8 + grp) * ROWB + kk * 2;
                u32 b0 = lds32(bAddr);
                u32 b1 = lds32(bAddr + 16);
#pragma unroll
                for (int mt = 0; mt < 3; mt++)
                    mma16816(acc[mt][j], a[mt][0], a[mt][1], a[mt][2], a[mt][3], b0, b1);
            }
        }
        __syncthreads();
    }

    // ---- epilogue: write split-K partials (all rows < 96 by construction) ----
#pragma unroll
    for (int mt = 0; mt < 3; mt++) {
        int br0 = m_w + mt * 16 + grp;
        int br1 = br0 + 8;
#pragma unroll
        for (int j = 0; j < 4; j++) {
            int col = n0 + n_off + j * 8 + (lane & 3) * 2;
            *(float2*)(d_part + ((size_t)z * NB + br0) * NTOT + col) =
                make_float2(acc[mt][j][0], acc[mt][j][1]);
            *(float2*)(d_part + ((size_t)z * NB + br1) * NTOT + col) =
                make_float2(acc[mt][j][2], acc[mt][j][3]);
        }
    }
}

// ---------------- reduce + phi + Euler update + A'' split write ----------------
// One thread per (batch, neuron-pair). Interleaved partial layout makes each
// z-slice contribution a single float4: (mu(2p), s2(2p), mu(2p+1), s2(2p+1)).
__global__ void k_update(int first, int last, float* __restrict__ out) {
    int tid = blockIdx.x * blockDim.x + threadIdx.x;
    if (tid >= UTOT) return;
    int b = tid / NPAIR;
    int p = tid - b * NPAIR;
    int i0 = 2 * p;

    float ms0 = 0.0f, ss0 = 0.0f, ms1 = 0.0f, ss1 = 0.0f;
    float rold0 = 0.0f, rold1 = 0.0f;
    if (!first) {
        float2 ro = *(const float2*)(d_rate + (size_t)b * NN + i0);
        rold0 = ro.x; rold1 = ro.y;
        const float* pp = d_part + (size_t)b * NTOT + 4 * p;
#pragma unroll
        for (int z = 0; z < KSP; z++) {
            float4 v = *(const float4*)(pp + (size_t)z * NB * NTOT);
            ms0 += v.x; ss0 += v.y; ms1 += v.z; ss1 += v.w;
        }
    }
    float2 mn = *(const float2*)(d_mean + (size_t)b * NN + i0);
    float mu0  = 0.01f * ms0 + mn.x;
    float mu1  = 0.01f * ms1 + mn.y;
    float sig0 = sqrtf(0.01f * ss0 + 25.0f);
    float sig1 = sqrtf(0.01f * ss1 + 25.0f);
    float tr = (i0 < NE) ? 0.005f : 0.001f;          // pair never straddles NE (1200 even)
    float aT = (i0 < NE) ? 0.1f : 0.2f;
    float rnew0 = rold0 + aT * (phi_f(mu0, sig0, tr) - rold0);
    float rnew1 = rold1 + aT * (phi_f(mu1, sig1, tr) - rold1);
    *(float2*)(d_rate + (size_t)b * NN + i0) = make_float2(rnew0, rnew1);

    // A'' split: segments [ah | ah | al] matching B'' [wh | wl | wh]
    __nv_bfloat16 ah0 = __float2bfloat16(rnew0);
    __nv_bfloat16 al0 = __float2bfloat16(rnew0 - __bfloat162float(ah0));
    __nv_bfloat16 ah1 = __float2bfloat16(rnew1);
    __nv_bfloat16 al1 = __float2bfloat16(rnew1 - __bfloat162float(ah1));
    __nv_bfloat162 hh; hh.x = ah0; hh.y = ah1;
    __nv_bfloat162 ll; ll.x = al0; ll.y = al1;
    size_t ar = (size_t)b * KTOT + i0;
    *(__nv_bfloat162*)(d_A + ar)            = hh;
    *(__nv_bfloat162*)(d_A + ar + NSEG)     = hh;
    *(__nv_bfloat162*)(d_A + ar + 2 * NSEG) = ll;

    if (last) {                                      // out[n][b] = rate[b][n]
        out[(size_t)i0 * NB + b] = rnew0;
        out[(size_t)(i0 + 1) * NB + b] = rnew1;
    }
}

// ---------------- launch ----------------
extern "C" void kernel_launch(void* const* d_in, const int* in_sizes, int n_in,
                              void* d_out, int out_size) {
    const float* hyp = (const float*)d_in[0];
    const float* rnd = (const float*)d_in[1];
    float* out = (float*)d_out;

    cudaFuncSetAttribute(k_mma, cudaFuncAttributeMaxDynamicSharedMemorySize, SMEM_TOTAL);

    k_weightsB<<<(NSEG * NSEG + 255) / 256, 256>>>(hyp, rnd);
    k_mean<<<(NB * NN + 255) / 256, 256>>>();
    k_zeroA<<<(MM * KTOT + 255) / 256, 256>>>();

    const int UB = (UTOT + 255) / 256;
    k_update<<<UB, 256>>>(1, 0, out);                 // step 1: rate=0 -> mu=mean
    for (int s = 1; s < NSTEPS; s++) {
        k_mma<<<dim3(NTILES, KSP), 256, SMEM_TOTAL>>>();
        k_update<<<UB, 256>>>(0, s == NSTEPS - 1 ? 1 : 0, out);
    }
}

// round 8
// speedup vs baseline: 5.4799x; 1.0403x over previous
#include <cuda_runtime.h>
#include <cuda_bf16.h>
#include <math.h>
#include <cstdint>

#define NN 1500
#define NE 1200
#define NB 96
#define NSEG 1536
#define KTOT 4608          // 3*NSEG
#define NTOT 3072          // 2*NSEG (interleaved: row 2n=mu(n), 2n+1=s2(n))
#define MM 96              // batch rows (6 x m16)
#define NT 128             // N-tile per CTA
#define NTILES 24          // NTOT/NT
#define KSP 12             // split-K
#define KCTA 384           // KTOT/KSP
#define KCH 64             // bf16 K per smem chunk
#define CH 6               // KCTA/KCH
#define NSTEPS 60
#define UTOT (NB * NN)     // update threads (one per batch,neuron)

// padded smem row: 64 bf16 data + 8 pad = 72 bf16 = 144 bytes (conflict-free frags)
#define ROWB 144
#define TILEA (MM * ROWB)            // 13824
#define TILEB_ (NT * ROWB)           // 18432
#define BUFSZ (TILEA + TILEB_)       // 32256
#define SMEM_TOTAL (2 * BUFSZ)       // 64512

typedef unsigned int u32;
typedef unsigned long long u64;

// ---------------- static device buffers ----------------
__device__ __align__(16) __nv_bfloat16 d_A[(size_t)MM * KTOT];     // [b][k]
__device__ __align__(16) __nv_bfloat16 d_B[(size_t)NTOT * KTOT];   // [r][k] 28.3MB
__device__ __align__(16) float d_part[(size_t)KSP * NB * NTOT];    // 14.2MB
__device__ __align__(16) float d_rate[NB * NN];
__device__ __align__(16) float d_mean[NB * NN];

__constant__ float c_contr[8] = {0.0f, 0.0432773f, 0.103411f, 0.186966f,
                                 0.303066f, 0.464386f, 0.68854f, 1.0f};

// ---------------- PTX helpers (base ISA only) ----------------
__device__ __forceinline__ u32 smem_u32(const void* p) {
    u32 a;
    asm("{ .reg .u64 t; cvta.to.shared.u64 t, %1; cvt.u32.u64 %0, t; }" : "=r"(a) : "l"(p));
    return a;
}
__device__ __forceinline__ u32 lds32(u32 addr) {
    u32 v;
    asm volatile("ld.shared.b32 %0, [%1];" : "=r"(v) : "r"(addr));
    return v;
}
__device__ __forceinline__ void cpasync16(u32 saddr, const void* gaddr) {
    asm volatile("cp.async.cg.shared.global [%0], [%1], 16;" :: "r"(saddr), "l"(gaddr));
}
__device__ __forceinline__ void mma16816(float* c, u32 a0, u32 a1, u32 a2, u32 a3,
                                         u32 b0, u32 b1) {
    asm volatile("mma.sync.aligned.m16n8k16.row.col.f32.bf16.bf16.f32 "
                 "{%0,%1,%2,%3}, {%4,%5,%6,%7}, {%8,%9}, {%0,%1,%2,%3};"
                 : "+f"(c[0]), "+f"(c[1]), "+f"(c[2]), "+f"(c[3])
                 : "r"(a0), "r"(a1), "r"(a2), "r"(a3), "r"(b0), "r"(b1));
}

// ---------------- math helpers ----------------
__device__ __forceinline__ float prefv(int n) {
    const float se = 179.99f / 1200.0f;
    const float si = 179.99f / 300.0f;
    return (n < NE) ? (float)n * se : (float)(n - NE) * si;
}
__device__ __forceinline__ float f_ricci(float x) {
    float z = x / (1.0f + x);
    float t = -z;
    float p = 0.14805913578876898f;
    p = p * t + 0.64290613877355551f;
    p = p * t + 1.0616084849547165f;
    p = p * t + 0.93524391761244940f;
    p = p * t + 0.62718906618071668f;
    p = p * t + 0.32171431660633076f;
    p = p * t + 0.32056016125642045f;
    p = p * t + 0.77373949685442023f;
    p = p * t + 0.22757881388024176f;
    p = p * t + 0.0f;
    return logf(2.0f * x + 1.0f) + p;
}
__device__ __forceinline__ float g_ricci(float x) {
    float z = x / (2.0f + x);
    float num = z * (3.5441754117462949f + z * (-7.0529131065835378f + z * (-56.532378057580381f
              + z * (279.56761105465944f + z * (-520.37554849441472f + z * (456.58245777026514f
              + z * (-155.73340457809226f)))))));
    float den = 1.0f + z * (-4.1357968834226053f + z * (-7.2984226138266743f + z * (98.656602235468327f
              + z * (-334.20436223415163f + z * (601.08633903294185f + z * (-599.58577549598340f
              + z * (277.18420330693891f + z * (-16.445022798669722f))))))));
    return num / den;
}
__device__ __forceinline__ float phi_f(float mu, float sig, float tau_ref) {
    const float tau = 0.01f;
    float xp = mu / sig;
    float xm = (mu - 20.0f) / sig;
    float r0;
    if (xm > 0.0f) {
        r0 = 1.0f / (f_ricci(xp) - f_ricci(xm));
    } else if (xp > 0.0f) {
        r0 = 1.0f / (f_ricci(xp) + expf(xm * xm) * g_ricci(-xm));
    } else {
        r0 = expf(-xm * xm - logf(g_ricci(-xm) - expf(xp * xp - xm * xm) * g_ricci(-xp)));
    }
    r0 = fmaxf(r0, 1e-30f);
    return 1.0f / (tau_ref + tau / r0);
}

// ---------------- setup kernels ----------------
// B'' row 2i   (mu neuron i): K segments [wh  | wl  | wh ]
// B'' row 2i+1 (s2 neuron i): K segments [w2h | w2l | w2h]
// paired with A'' segments [ah | ah | al] -> w*a ≈ wh*ah + wl*ah + wh*al
__global__ void k_weightsB(const float* __restrict__ hyp, const float* __restrict__ rnd) {
    int tid = blockIdx.x * blockDim.x + threadIdx.x;
    if (tid >= NSEG * NSEG) return;
    int i = tid / NSEG;          // output neuron
    int j = tid - i * NSEG;      // input neuron (K)
    float w = 0.0f;
    if (i < NN && j < NN) {
        int conn = (i >= NE ? 1 : 0) + 2 * (j >= NE ? 1 : 0);
        float J = hyp[conn], P = hyp[4 + conn], Wp = hyp[8 + conn];
        const float cd = 3.14159265358979323846f / 180.0f;
        float diff = fabsf(prefv(i) - prefv(j));
        float wden = 4.0f * (cd * Wp) * (cd * Wp);
        float z = expf((cosf(2.0f * cd * diff) - 1.0f) / wden);
        float x = 32.0f * (P * z - rnd[(size_t)i * NN + j]);
        w = J / (1.0f + expf(-x));
    }
    float w2 = w * w;
    __nv_bfloat16 wh = __float2bfloat16(w);
    __nv_bfloat16 wl = __float2bfloat16(w - __bfloat162float(wh));
    __nv_bfloat16 vh = __float2bfloat16(w2);
    __nv_bfloat16 vl = __float2bfloat16(w2 - __bfloat162float(vh));
    size_t r1 = (size_t)(2 * i) * KTOT;
    size_t r2 = (size_t)(2 * i + 1) * KTOT;
    d_B[r1 + j] = wh; d_B[r1 + NSEG + j] = wl; d_B[r1 + 2 * NSEG + j] = wh;
    d_B[r2 + j] = vh; d_B[r2 + NSEG + j] = vl; d_B[r2 + 2 * NSEG + j] = vh;
}

__global__ void k_mean() {
    int tid = blockIdx.x * blockDim.x + threadIdx.x;
    if (tid >= NB * NN) return;
    int b = tid / NN;
    int n = tid - b * NN;
    int c = b / 12;
    int o = b - c * 12;
    const float cd = 3.14159265358979323846f / 180.0f;
    float dth = (float)o * 15.0f - prefv(n);
    const float wden = 4.0f * (cd * 30.0f) * (cd * 30.0f);
    float cg = expf((cosf(2.0f * cd * dth) - 1.0f) / wden);
    d_mean[tid] = c_contr[c] * 20.0f * cg;
}

// split in two so that launch index 5 (ncu -s 5 -c 1) lands on k_mma
__global__ void k_zeroA1() {
    int tid = blockIdx.x * blockDim.x + threadIdx.x;
    if (tid < MM * KTOT / 2) d_A[tid] = __float2bfloat16(0.0f);
}
__global__ void k_zeroA2() {
    int tid = blockIdx.x * blockDim.x + threadIdx.x;
    if (tid < MM * KTOT / 2) d_A[MM * KTOT / 2 + tid] = __float2bfloat16(0.0f);
}

// ---------------- bf16 mma.sync GEMM step ----------------
// grid (24 n-tiles, 12 split-K), 256 threads.
// Per CTA: D[96,128] = A''[96, 384-slice] * B''tile^T, cp.async double-buffered.
// Warp layout 2(m)x4(n); warp tile 48x32 = 3 m-frags x 4 n-frags.
__global__ __launch_bounds__(256, 2) void k_mma() {
    extern __shared__ char sm[];
    u32 sb = smem_u32(sm);
    const int tid = threadIdx.x, wid = tid >> 5, lane = tid & 31;
    const int n0 = blockIdx.x * NT;
    const int z = blockIdx.y;
    const int kbase = z * KCTA;

    const char* Agc = (const char*)d_A;
    const char* Bgc = (const char*)d_B;

    float acc[3][4][4];
#pragma unroll
    for (int mt = 0; mt < 3; mt++)
#pragma unroll
        for (int j = 0; j < 4; j++)
#pragma unroll
            for (int q = 0; q < 4; q++) acc[mt][j][q] = 0.0f;

    const int m_w = (wid & 1) * 48;
    const int n_off = (wid >> 1) * 32;
    const int grp = lane >> 2;          // 0..7
    const int kq = (lane & 3) * 2;      // 0,2,4,6 (bf16 halves)

    // ---- prefetch chunk 0 ----
    {
        int kg = kbase;
        u32 bufA = sb, bufB = sb + TILEA;
#pragma unroll
        for (int it = 0; it < 3; it++) {         // A: 96 rows x 8 quads = 768
            int u = tid + 256 * it; int row = u >> 3; int wq = u & 7;
            cpasync16(bufA + row * ROWB + wq * 16,
                      Agc + ((size_t)row * KTOT + kg + wq * 8) * 2);
        }
#pragma unroll
        for (int it = 0; it < 4; it++) {         // B: 128 rows x 8 quads = 1024
            int u = tid + 256 * it; int row = u >> 3; int wq = u & 7;
            cpasync16(bufB + row * ROWB + wq * 16,
                      Bgc + ((size_t)(n0 + row) * KTOT + kg + wq * 8) * 2);
        }
        asm volatile("cp.async.commit_group;" ::: "memory");
    }

    for (int c = 0; c < CH; c++) {
        if (c < CH - 1) {               // prefetch next chunk into other buffer
            int kg = kbase + (c + 1) * KCH;
            u32 bufA = sb + (((c + 1) & 1) ? (u32)BUFSZ : 0u);
            u32 bufB = bufA + TILEA;
#pragma unroll
            for (int it = 0; it < 3; it++) {
                int u = tid + 256 * it; int row = u >> 3; int wq = u & 7;
                cpasync16(bufA + row * ROWB + wq * 16,
                          Agc + ((size_t)row * KTOT + kg + wq * 8) * 2);
            }
#pragma unroll
            for (int it = 0; it < 4; it++) {
                int u = tid + 256 * it; int row = u >> 3; int wq = u & 7;
                cpasync16(bufB + row * ROWB + wq * 16,
                          Bgc + ((size_t)(n0 + row) * KTOT + kg + wq * 8) * 2);
            }
            asm volatile("cp.async.commit_group;" ::: "memory");
            asm volatile("cp.async.wait_group 1;" ::: "memory");
        } else {
            asm volatile("cp.async.wait_group 0;" ::: "memory");
        }
        __syncthreads();

        u32 bufA = sb + ((c & 1) ? (u32)BUFSZ : 0u);
        u32 bufB = bufA + TILEA;

#pragma unroll
        for (int ks = 0; ks < 4; ks++) {
            int kk = ks * 16 + kq;
            u32 a[3][4];
#pragma unroll
            for (int mt = 0; mt < 3; mt++) {
                u32 aAddr = bufA + (m_w + mt * 16 + grp) * ROWB + kk * 2;
                a[mt][0] = lds32(aAddr);
                a[mt][1] = lds32(aAddr + 8 * ROWB);
                a[mt][2] = lds32(aAddr + 16);
                a[mt][3] = lds32(aAddr + 8 * ROWB + 16);
            }
#pragma unroll
            for (int j = 0; j < 4; j++) {
                u32 bAddr = bufB + (n_off + j * 8 + grp) * ROWB + kk * 2;
                u32 b0 = lds32(bAddr);
                u32 b1 = lds32(bAddr + 16);
#pragma unroll
                for (int mt = 0; mt < 3; mt++)
                    mma16816(acc[mt][j], a[mt][0], a[mt][1], a[mt][2], a[mt][3], b0, b1);
            }
        }
        __syncthreads();
    }

    // ---- epilogue: write split-K partials (all rows < 96 by construction) ----
#pragma unroll
    for (int mt = 0; mt < 3; mt++) {
        int br0 = m_w + mt * 16 + grp;
        int br1 = br0 + 8;
#pragma unroll
        for (int j = 0; j < 4; j++) {
            int col = n0 + n_off + j * 8 + (lane & 3) * 2;
            *(float2*)(d_part + ((size_t)z * NB + br0) * NTOT + col) =
                make_float2(acc[mt][j][0], acc[mt][j][1]);
            *(float2*)(d_part + ((size_t)z * NB + br1) * NTOT + col) =
                make_float2(acc[mt][j][2], acc[mt][j][3]);
        }
    }
}

// ---------------- reduce + phi + Euler update + A'' split write ----------------
// One thread per (batch, neuron): max thread count for latency hiding; the
// interleaved layout still gives (mu, s2) as a single float2 per z-slice.
__global__ void k_update(int first, int last, float* __restrict__ out) {
    int tid = blockIdx.x * blockDim.x + threadIdx.x;
    if (tid >= UTOT) return;
    int b = tid / NN;
    int n = tid - b * NN;

    float ms = 0.0f, ss = 0.0f, rold = 0.0f;
    if (!first) {
        rold = d_rate[tid];
        const float* pp = d_part + (size_t)b * NTOT + 2 * n;
#pragma unroll
        for (int z = 0; z < KSP; z++) {
            float2 v = *(const float2*)(pp + (size_t)z * NB * NTOT);
            ms += v.x; ss += v.y;
        }
    }
    float mu  = 0.01f * ms + d_mean[tid];
    float sig = sqrtf(0.01f * ss + 25.0f);
    float tr = (n < NE) ? 0.005f : 0.001f;
    float aT = (n < NE) ? 0.1f : 0.2f;
    float ph = phi_f(mu, sig, tr);
    float rnew = rold + aT * (ph - rold);
    d_rate[tid] = rnew;

    // A'' split: segments [ah | ah | al] matching B'' [wh | wl | wh]
    __nv_bfloat16 ah = __float2bfloat16(rnew);
    __nv_bfloat16 al = __float2bfloat16(rnew - __bfloat162float(ah));
    size_t ar = (size_t)b * KTOT + n;
    d_A[ar]            = ah;
    d_A[ar + NSEG]     = ah;
    d_A[ar + 2 * NSEG] = al;

    if (last) out[(size_t)n * NB + b] = rnew;        // out[n][b] = rate[b][n]
}

// ---------------- launch ----------------
extern "C" void kernel_launch(void* const* d_in, const int* in_sizes, int n_in,
                              void* d_out, int out_size) {
    const float* hyp = (const float*)d_in[0];
    const float* rnd = (const float*)d_in[1];
    float* out = (float*)d_out;

    cudaFuncSetAttribute(k_mma, cudaFuncAttributeMaxDynamicSharedMemorySize, SMEM_TOTAL);

    k_weightsB<<<(NSEG * NSEG + 255) / 256, 256>>>(hyp, rnd);    // launch 0
    k_mean<<<(NB * NN + 255) / 256, 256>>>();                    // launch 1
    k_zeroA1<<<(MM * KTOT / 2 + 255) / 256, 256>>>();            // launch 2
    k_zeroA2<<<(MM * KTOT / 2 + 255) / 256, 256>>>();            // launch 3

    const int UB = (UTOT + 255) / 256;
    k_update<<<UB, 256>>>(1, 0, out);                            // launch 4
    for (int s = 1; s < NSTEPS; s++) {
        k_mma<<<dim3(NTILES, KSP), 256, SMEM_TOTAL>>>();         // launch 5 = profiled
        k_update<<<UB, 256>>>(0, s == NSTEPS - 1 ? 1 : 0, out);
    }
}

// round 10
// speedup vs baseline: 5.7271x; 1.0451x over previous
#include <cuda_runtime.h>
#include <cuda_bf16.h>
#include <math.h>
#include <cstdint>

#define NN 1500
#define NE 1200
#define NB 96
#define NSEG 1536
#define KTOT 4608          // 3*NSEG
#define NTOT 3072          // 2*NSEG (interleaved: row 2n=mu(n), 2n+1=s2(n))
#define MM 96              // batch rows (6 x m16)
#define NT 128             // N-tile per CTA
#define NTILES 24          // NTOT/NT
#define KSP 12             // split-K
#define KCTA 384           // KTOT/KSP
#define KCH 64             // bf16 K per smem chunk
#define CH 6               // KCTA/KCH
#define NSTEPS 60
#define UTOT (NB * NN)     // update threads (one per batch,neuron)

// padded smem row: 64 bf16 data + 8 pad = 72 bf16 = 144 bytes (conflict-free frags)
#define ROWB 144
#define TILEA (MM * ROWB)            // 13824
#define TILEB_ (NT * ROWB)           // 18432
#define BUFSZ (TILEA + TILEB_)       // 32256
#define SMEM_TOTAL (3 * BUFSZ)       // 96768 (triple buffer)

typedef unsigned int u32;
typedef unsigned long long u64;

// ---------------- static device buffers ----------------
__device__ __align__(16) __nv_bfloat16 d_A[(size_t)MM * KTOT];     // [b][k]
__device__ __align__(16) __nv_bfloat16 d_B[(size_t)NTOT * KTOT];   // [r][k] 28.3MB
__device__ __align__(16) float d_part[(size_t)KSP * NB * NTOT];    // 14.2MB
__device__ __align__(16) float d_rate[NB * NN];
__device__ __align__(16) float d_mean[NB * NN];

__constant__ float c_contr[8] = {0.0f, 0.0432773f, 0.103411f, 0.186966f,
                                 0.303066f, 0.464386f, 0.68854f, 1.0f};

// ---------------- PTX helpers (base ISA only) ----------------
__device__ __forceinline__ u32 smem_u32(const void* p) {
    u32 a;
    asm("{ .reg .u64 t; cvta.to.shared.u64 t, %1; cvt.u32.u64 %0, t; }" : "=r"(a) : "l"(p));
    return a;
}
__device__ __forceinline__ u32 lds32(u32 addr) {
    u32 v;
    asm volatile("ld.shared.b32 %0, [%1];" : "=r"(v) : "r"(addr));
    return v;
}
__device__ __forceinline__ void cpasync16(u32 saddr, const void* gaddr) {
    asm volatile("cp.async.cg.shared.global [%0], [%1], 16;" :: "r"(saddr), "l"(gaddr));
}
__device__ __forceinline__ void mma16816(float* c, u32 a0, u32 a1, u32 a2, u32 a3,
                                         u32 b0, u32 b1) {
    asm volatile("mma.sync.aligned.m16n8k16.row.col.f32.bf16.bf16.f32 "
                 "{%0,%1,%2,%3}, {%4,%5,%6,%7}, {%8,%9}, {%0,%1,%2,%3};"
                 : "+f"(c[0]), "+f"(c[1]), "+f"(c[2]), "+f"(c[3])
                 : "r"(a0), "r"(a1), "r"(a2), "r"(a3), "r"(b0), "r"(b1));
}

// ---------------- math helpers ----------------
__device__ __forceinline__ float prefv(int n) {
    const float se = 179.99f / 1200.0f;
    const float si = 179.99f / 300.0f;
    return (n < NE) ? (float)n * se : (float)(n - NE) * si;
}
__device__ __forceinline__ float f_ricci(float x) {
    float z = x / (1.0f + x);
    float t = -z;
    float p = 0.14805913578876898f;
    p = p * t + 0.64290613877355551f;
    p = p * t + 1.0616084849547165f;
    p = p * t + 0.93524391761244940f;
    p = p * t + 0.62718906618071668f;
    p = p * t + 0.32171431660633076f;
    p = p * t + 0.32056016125642045f;
    p = p * t + 0.77373949685442023f;
    p = p * t + 0.22757881388024176f;
    p = p * t + 0.0f;
    return logf(2.0f * x + 1.0f) + p;
}
__device__ __forceinline__ float g_ricci(float x) {
    float z = x / (2.0f + x);
    float num = z * (3.5441754117462949f + z * (-7.0529131065835378f + z * (-56.532378057580381f
              + z * (279.56761105465944f + z * (-520.37554849441472f + z * (456.58245777026514f
              + z * (-155.73340457809226f)))))));
    float den = 1.0f + z * (-4.1357968834226053f + z * (-7.2984226138266743f + z * (98.656602235468327f
              + z * (-334.20436223415163f + z * (601.08633903294185f + z * (-599.58577549598340f
              + z * (277.18420330693891f + z * (-16.445022798669722f))))))));
    return num / den;
}
__device__ __forceinline__ float phi_f(float mu, float sig, float tau_ref) {
    const float tau = 0.01f;
    float xp = mu / sig;
    float xm = (mu - 20.0f) / sig;
    float r0;
    if (xm > 0.0f) {
        r0 = 1.0f / (f_ricci(xp) - f_ricci(xm));
    } else if (xp > 0.0f) {
        r0 = 1.0f / (f_ricci(xp) + expf(xm * xm) * g_ricci(-xm));
    } else {
        r0 = expf(-xm * xm - logf(g_ricci(-xm) - expf(xp * xp - xm * xm) * g_ricci(-xp)));
    }
    r0 = fmaxf(r0, 1e-30f);
    return 1.0f / (tau_ref + tau / r0);
}

// ---------------- setup kernels ----------------
// B'' row 2i   (mu neuron i): K segments [wh  | wl  | wh ]
// B'' row 2i+1 (s2 neuron i): K segments [w2h | w2l | w2h]
// paired with A'' segments [ah | ah | al] -> w*a ≈ wh*ah + wl*ah + wh*al
__global__ void k_weightsB(const float* __restrict__ hyp, const float* __restrict__ rnd) {
    int tid = blockIdx.x * blockDim.x + threadIdx.x;
    if (tid >= NSEG * NSEG) return;
    int i = tid / NSEG;          // output neuron
    int j = tid - i * NSEG;      // input neuron (K)
    float w = 0.0f;
    if (i < NN && j < NN) {
        int conn = (i >= NE ? 1 : 0) + 2 * (j >= NE ? 1 : 0);
        float J = hyp[conn], P = hyp[4 + conn], Wp = hyp[8 + conn];
        const float cd = 3.14159265358979323846f / 180.0f;
        float diff = fabsf(prefv(i) - prefv(j));
        float wden = 4.0f * (cd * Wp) * (cd * Wp);
        float z = expf((cosf(2.0f * cd * diff) - 1.0f) / wden);
        float x = 32.0f * (P * z - rnd[(size_t)i * NN + j]);
        w = J / (1.0f + expf(-x));
    }
    float w2 = w * w;
    __nv_bfloat16 wh = __float2bfloat16(w);
    __nv_bfloat16 wl = __float2bfloat16(w - __bfloat162float(wh));
    __nv_bfloat16 vh = __float2bfloat16(w2);
    __nv_bfloat16 vl = __float2bfloat16(w2 - __bfloat162float(vh));
    size_t r1 = (size_t)(2 * i) * KTOT;
    size_t r2 = (size_t)(2 * i + 1) * KTOT;
    d_B[r1 + j] = wh; d_B[r1 + NSEG + j] = wl; d_B[r1 + 2 * NSEG + j] = wh;
    d_B[r2 + j] = vh; d_B[r2 + NSEG + j] = vl; d_B[r2 + 2 * NSEG + j] = vh;
}

__global__ void k_mean() {
    int tid = blockIdx.x * blockDim.x + threadIdx.x;
    if (tid >= NB * NN) return;
    int b = tid / NN;
    int n = tid - b * NN;
    int c = b / 12;
    int o = b - c * 12;
    const float cd = 3.14159265358979323846f / 180.0f;
    float dth = (float)o * 15.0f - prefv(n);
    const float wden = 4.0f * (cd * 30.0f) * (cd * 30.0f);
    float cg = expf((cosf(2.0f * cd * dth) - 1.0f) / wden);
    d_mean[tid] = c_contr[c] * 20.0f * cg;
}

__global__ void k_zeroA() {
    int tid = blockIdx.x * blockDim.x + threadIdx.x;
    if (tid < MM * KTOT) d_A[tid] = __float2bfloat16(0.0f);
}

// ---------------- bf16 mma.sync GEMM step ----------------
// grid (24 n-tiles, 12 split-K), 256 threads.
// Per CTA: D[96,128] = A''[96, 384-slice] * B''tile^T.
// Triple-buffered cp.async pipeline, prefetch distance 2, one barrier per chunk.
// Correct ordering per chunk c: wait_group -> __syncthreads -> prefetch c+2 -> compute c.
// The barrier both publishes chunk c's smem AND proves all warps are done reading
// buffer (c-1)%3, which is exactly the buffer chunk c+2 refills.
__global__ __launch_bounds__(256, 2) void k_mma() {
    extern __shared__ char sm[];
    u32 sb = smem_u32(sm);
    const int tid = threadIdx.x, wid = tid >> 5, lane = tid & 31;
    const int n0 = blockIdx.x * NT;
    const int z = blockIdx.y;
    const int kbase = z * KCTA;

    const char* Agc = (const char*)d_A;
    const char* Bgc = (const char*)d_B;

    float acc[3][4][4];
#pragma unroll
    for (int mt = 0; mt < 3; mt++)
#pragma unroll
        for (int j = 0; j < 4; j++)
#pragma unroll
            for (int q = 0; q < 4; q++) acc[mt][j][q] = 0.0f;

    const int m_w = (wid & 1) * 48;
    const int n_off = (wid >> 1) * 32;
    const int grp = lane >> 2;          // 0..7
    const int kq = (lane & 3) * 2;      // 0,2,4,6 (bf16 halves)

    // per-thread fixed load slots
    const int rowA = tid >> 3, wq = tid & 7;

    // ---- prologue: prefetch chunks 0 and 1 ----
#pragma unroll
    for (int pc = 0; pc < 2; pc++) {
        int kg = kbase + pc * KCH;
        u32 bufA = sb + pc * (u32)BUFSZ;
        u32 bufB = bufA + TILEA;
#pragma unroll
        for (int it = 0; it < 3; it++) {         // A: 96 rows x 8 quads
            int row = rowA + 32 * it;
            cpasync16(bufA + row * ROWB + wq * 16,
                      Agc + ((size_t)row * KTOT + kg + wq * 8) * 2);
        }
#pragma unroll
        for (int it = 0; it < 4; it++) {         // B: 128 rows x 8 quads
            int row = rowA + 32 * it;
            cpasync16(bufB + row * ROWB + wq * 16,
                      Bgc + ((size_t)(n0 + row) * KTOT + kg + wq * 8) * 2);
        }
        asm volatile("cp.async.commit_group;" ::: "memory");
    }

#pragma unroll
    for (int c = 0; c < CH; c++) {
        // 1) chunk c's copies complete (per-thread)...
        if (c < CH - 1) {
            asm volatile("cp.async.wait_group 1;" ::: "memory");
        } else {
            asm volatile("cp.async.wait_group 0;" ::: "memory");
        }
        // 2) ...and visible to every thread; also: everyone is done with buffer (c-1)%3
        __syncthreads();

        // 3) refill buffer (c+2)%3 == (c-1)%3
        if (c + 2 < CH) {
            int kg = kbase + (c + 2) * KCH;
            u32 bufA = sb + ((c + 2) % 3) * (u32)BUFSZ;
            u32 bufB = bufA + TILEA;
#pragma unroll
            for (int it = 0; it < 3; it++) {
                int row = rowA + 32 * it;
                cpasync16(bufA + row * ROWB + wq * 16,
                          Agc + ((size_t)row * KTOT + kg + wq * 8) * 2);
            }
#pragma unroll
            for (int it = 0; it < 4; it++) {
                int row = rowA + 32 * it;
                cpasync16(bufB + row * ROWB + wq * 16,
                          Bgc + ((size_t)(n0 + row) * KTOT + kg + wq * 8) * 2);
            }
            asm volatile("cp.async.commit_group;" ::: "memory");
        }

        // 4) compute chunk c
        u32 bufA = sb + (c % 3) * (u32)BUFSZ;
        u32 bufB = bufA + TILEA;

#pragma unroll
        for (int ks = 0; ks < 4; ks++) {
            int kk = ks * 16 + kq;
            u32 a[3][4];
#pragma unroll
            for (int mt = 0; mt < 3; mt++) {
                u32 aAddr = bufA + (m_w + mt * 16 + grp) * ROWB + kk * 2;
                a[mt][0] = lds32(aAddr);
                a[mt][1] = lds32(aAddr + 8 * ROWB);
                a[mt][2] = lds32(aAddr + 16);
                a[mt][3] = lds32(aAddr + 8 * ROWB + 16);
            }
#pragma unroll
            for (int j = 0; j < 4; j++) {
                u32 bAddr = bufB + (n_off + j * 8 + grp) * ROWB + kk * 2;
                u32 b0 = lds32(bAddr);
                u32 b1 = lds32(bAddr + 16);
#pragma unroll
                for (int mt = 0; mt < 3; mt++)
                    mma16816(acc[mt][j], a[mt][0], a[mt][1], a[mt][2], a[mt][3], b0, b1);
            }
        }
    }

    // ---- epilogue: write split-K partials (all rows < 96 by construction) ----
#pragma unroll
    for (int mt = 0; mt < 3; mt++) {
        int br0 = m_w + mt * 16 + grp;
        int br1 = br0 + 8;
#pragma unroll
        for (int j = 0; j < 4; j++) {
            int col = n0 + n_off + j * 8 + (lane & 3) * 2;
            *(float2*)(d_part + ((size_t)z * NB + br0) * NTOT + col) =
                make_float2(acc[mt][j][0], acc[mt][j][1]);
            *(float2*)(d_part + ((size_t)z * NB + br1) * NTOT + col) =
                make_float2(acc[mt][j][2], acc[mt][j][3]);
        }
    }
}

// ---------------- reduce + phi + Euler update + A'' split write ----------------
// One thread per (batch, neuron); (mu, s2) arrive as one float2 per z-slice.
__global__ void k_update(int first, int last, float* __restrict__ out) {
    int tid = blockIdx.x * blockDim.x + threadIdx.x;
    if (tid >= UTOT) return;
    int b = tid / NN;
    int n = tid - b * NN;

    float ms = 0.0f, ss = 0.0f, rold = 0.0f;
    if (!first) {
        rold = d_rate[tid];
        const float* pp = d_part + (size_t)b * NTOT + 2 * n;
#pragma unroll
        for (int z = 0; z < KSP; z++) {
            float2 v = *(const float2*)(pp + (size_t)z * NB * NTOT);
            ms += v.x; ss += v.y;
        }
    }
    float mu  = 0.01f * ms + d_mean[tid];
    float sig = sqrtf(0.01f * ss + 25.0f);
    float tr = (n < NE) ? 0.005f : 0.001f;
    float aT = (n < NE) ? 0.1f : 0.2f;
    float ph = phi_f(mu, sig, tr);
    float rnew = rold + aT * (ph - rold);
    d_rate[tid] = rnew;

    // A'' split: segments [ah | ah | al] matching B'' [wh | wl | wh]
    __nv_bfloat16 ah = __float2bfloat16(rnew);
    __nv_bfloat16 al = __float2bfloat16(rnew - __bfloat162float(ah));
    size_t ar = (size_t)b * KTOT + n;
    d_A[ar]            = ah;
    d_A[ar + NSEG]     = ah;
    d_A[ar + 2 * NSEG] = al;

    if (last) out[(size_t)n * NB + b] = rnew;        // out[n][b] = rate[b][n]
}

// ---------------- launch ----------------
extern "C" void kernel_launch(void* const* d_in, const int* in_sizes, int n_in,
                              void* d_out, int out_size) {
    const float* hyp = (const float*)d_in[0];
    const float* rnd = (const float*)d_in[1];
    float* out = (float*)d_out;

    cudaFuncSetAttribute(k_mma, cudaFuncAttributeMaxDynamicSharedMemorySize, SMEM_TOTAL);

    k_weightsB<<<(NSEG * NSEG + 255) / 256, 256>>>(hyp, rnd);
    k_mean<<<(NB * NN + 255) / 256, 256>>>();
    k_zeroA<<<(MM * KTOT + 255) / 256, 256>>>();

    const int UB = (UTOT + 255) / 256;
    k_update<<<UB, 256>>>(1, 0, out);                 // step 1: rate=0 -> mu=mean
    for (int s = 1; s < NSTEPS; s++) {
        k_mma<<<dim3(NTILES, KSP), 256, SMEM_TOTAL>>>();
        k_update<<<UB, 256>>>(0, s == NSTEPS - 1 ? 1 : 0, out);
    }
}

// round 11
// speedup vs baseline: 5.8348x; 1.0188x over previous
#include <cuda_runtime.h>
#include <cuda_bf16.h>
#include <math.h>
#include <cstdint>

#define NN 1500
#define NE 1200
#define NB 96
#define NSEG 1536
#define KTOT 4608          // 3*NSEG
#define NTOT 3072          // 2*NSEG (interleaved: row 2n=mu(n), 2n+1=s2(n))
#define MM 96              // batch rows (6 x m16)
#define NT 128             // N-tile per CTA
#define NTILES 24          // NTOT/NT
#define KSP 12             // split-K
#define KCTA 384           // KTOT/KSP
#define KCH 64             // bf16 K per smem chunk
#define CH 6               // KCTA/KCH
#define NSTEPS 60
#define UTOT (NB * NN)     // update threads (one per batch,neuron)

// padded smem row: 64 bf16 data + 8 pad = 72 bf16 = 144 bytes (conflict-free frags)
#define ROWB 144
#define TILEA (MM * ROWB)            // 13824
#define TILEB_ (NT * ROWB)           // 18432
#define BUFSZ (TILEA + TILEB_)       // 32256
#define SMEM_TOTAL (3 * BUFSZ)       // 96768 (triple buffer)

typedef unsigned int u32;
typedef unsigned long long u64;

// ---------------- static device buffers ----------------
__device__ __align__(16) __nv_bfloat16 d_A[(size_t)MM * KTOT];     // [b][k]
__device__ __align__(16) __nv_bfloat16 d_B[(size_t)NTOT * KTOT];   // [r][k] 28.3MB
__device__ __align__(16) float d_part[(size_t)KSP * NB * NTOT];    // 14.2MB
__device__ __align__(16) float d_rate[NB * NN];
__device__ __align__(16) float d_mean[NB * NN];

__constant__ float c_contr[8] = {0.0f, 0.0432773f, 0.103411f, 0.186966f,
                                 0.303066f, 0.464386f, 0.68854f, 1.0f};

// ---------------- PTX helpers (base ISA only) ----------------
__device__ __forceinline__ u32 smem_u32(const void* p) {
    u32 a;
    asm("{ .reg .u64 t; cvta.to.shared.u64 t, %1; cvt.u32.u64 %0, t; }" : "=r"(a) : "l"(p));
    return a;
}
__device__ __forceinline__ void ldsm4(u32& r0, u32& r1, u32& r2, u32& r3, u32 addr) {
    asm volatile("ldmatrix.sync.aligned.m8n8.x4.shared.b16 {%0,%1,%2,%3}, [%4];"
                 : "=r"(r0), "=r"(r1), "=r"(r2), "=r"(r3) : "r"(addr));
}
__device__ __forceinline__ void cpasync16(u32 saddr, const void* gaddr) {
    asm volatile("cp.async.cg.shared.global [%0], [%1], 16;" :: "r"(saddr), "l"(gaddr));
}
__device__ __forceinline__ void mma16816(float* c, u32 a0, u32 a1, u32 a2, u32 a3,
                                         u32 b0, u32 b1) {
    asm volatile("mma.sync.aligned.m16n8k16.row.col.f32.bf16.bf16.f32 "
                 "{%0,%1,%2,%3}, {%4,%5,%6,%7}, {%8,%9}, {%0,%1,%2,%3};"
                 : "+f"(c[0]), "+f"(c[1]), "+f"(c[2]), "+f"(c[3])
                 : "r"(a0), "r"(a1), "r"(a2), "r"(a3), "r"(b0), "r"(b1));
}

// ---------------- math helpers ----------------
__device__ __forceinline__ float prefv(int n) {
    const float se = 179.99f / 1200.0f;
    const float si = 179.99f / 300.0f;
    return (n < NE) ? (float)n * se : (float)(n - NE) * si;
}
__device__ __forceinline__ float f_ricci(float x) {
    float z = x / (1.0f + x);
    float t = -z;
    float p = 0.14805913578876898f;
    p = p * t + 0.64290613877355551f;
    p = p * t + 1.0616084849547165f;
    p = p * t + 0.93524391761244940f;
    p = p * t + 0.62718906618071668f;
    p = p * t + 0.32171431660633076f;
    p = p * t + 0.32056016125642045f;
    p = p * t + 0.77373949685442023f;
    p = p * t + 0.22757881388024176f;
    p = p * t + 0.0f;
    return logf(2.0f * x + 1.0f) + p;
}
__device__ __forceinline__ float g_ricci(float x) {
    float z = x / (2.0f + x);
    float num = z * (3.5441754117462949f + z * (-7.0529131065835378f + z * (-56.532378057580381f
              + z * (279.56761105465944f + z * (-520.37554849441472f + z * (456.58245777026514f
              + z * (-155.73340457809226f)))))));
    float den = 1.0f + z * (-4.1357968834226053f + z * (-7.2984226138266743f + z * (98.656602235468327f
              + z * (-334.20436223415163f + z * (601.08633903294185f + z * (-599.58577549598340f
              + z * (277.18420330693891f + z * (-16.445022798669722f))))))));
    return num / den;
}
__device__ __forceinline__ float phi_f(float mu, float sig, float tau_ref) {
    const float tau = 0.01f;
    float xp = mu / sig;
    float xm = (mu - 20.0f) / sig;
    float r0;
    if (xm > 0.0f) {
        r0 = 1.0f / (f_ricci(xp) - f_ricci(xm));
    } else if (xp > 0.0f) {
        r0 = 1.0f / (f_ricci(xp) + expf(xm * xm) * g_ricci(-xm));
    } else {
        r0 = expf(-xm * xm - logf(g_ricci(-xm) - expf(xp * xp - xm * xm) * g_ricci(-xp)));
    }
    r0 = fmaxf(r0, 1e-30f);
    return 1.0f / (tau_ref + tau / r0);
}

// ---------------- setup kernels ----------------
// B'' row 2i   (mu neuron i): K segments [wh  | wl  | wh ]
// B'' row 2i+1 (s2 neuron i): K segments [w2h | w2l | w2h]
// paired with A'' segments [ah | ah | al] -> w*a ≈ wh*ah + wl*ah + wh*al
__global__ void k_weightsB(const float* __restrict__ hyp, const float* __restrict__ rnd) {
    int tid = blockIdx.x * blockDim.x + threadIdx.x;
    if (tid >= NSEG * NSEG) return;
    int i = tid / NSEG;          // output neuron
    int j = tid - i * NSEG;      // input neuron (K)
    float w = 0.0f;
    if (i < NN && j < NN) {
        int conn = (i >= NE ? 1 : 0) + 2 * (j >= NE ? 1 : 0);
        float J = hyp[conn], P = hyp[4 + conn], Wp = hyp[8 + conn];
        const float cd = 3.14159265358979323846f / 180.0f;
        float diff = fabsf(prefv(i) - prefv(j));
        float wden = 4.0f * (cd * Wp) * (cd * Wp);
        float z = expf((cosf(2.0f * cd * diff) - 1.0f) / wden);
        float x = 32.0f * (P * z - rnd[(size_t)i * NN + j]);
        w = J / (1.0f + expf(-x));
    }
    float w2 = w * w;
    __nv_bfloat16 wh = __float2bfloat16(w);
    __nv_bfloat16 wl = __float2bfloat16(w - __bfloat162float(wh));
    __nv_bfloat16 vh = __float2bfloat16(w2);
    __nv_bfloat16 vl = __float2bfloat16(w2 - __bfloat162float(vh));
    size_t r1 = (size_t)(2 * i) * KTOT;
    size_t r2 = (size_t)(2 * i + 1) * KTOT;
    d_B[r1 + j] = wh; d_B[r1 + NSEG + j] = wl; d_B[r1 + 2 * NSEG + j] = wh;
    d_B[r2 + j] = vh; d_B[r2 + NSEG + j] = vl; d_B[r2 + 2 * NSEG + j] = vh;
}

__global__ void k_mean() {
    int tid = blockIdx.x * blockDim.x + threadIdx.x;
    if (tid >= NB * NN) return;
    int b = tid / NN;
    int n = tid - b * NN;
    int c = b / 12;
    int o = b - c * 12;
    const float cd = 3.14159265358979323846f / 180.0f;
    float dth = (float)o * 15.0f - prefv(n);
    const float wden = 4.0f * (cd * 30.0f) * (cd * 30.0f);
    float cg = expf((cosf(2.0f * cd * dth) - 1.0f) / wden);
    d_mean[tid] = c_contr[c] * 20.0f * cg;
}

__global__ void k_zeroA() {
    int tid = blockIdx.x * blockDim.x + threadIdx.x;
    if (tid < MM * KTOT) d_A[tid] = __float2bfloat16(0.0f);
}

// ---------------- bf16 mma.sync GEMM step ----------------
// grid (24 n-tiles, 12 split-K), 256 threads.
// Per CTA: D[96,128] = A''[96, 384-slice] * B''tile^T.
// Triple-buffered cp.async pipeline (distance 2, one barrier/chunk, validated R10).
// Fragments loaded via ldmatrix.x4 (5 LDSM per k-step vs 20 LDS.32).
__global__ __launch_bounds__(256, 2) void k_mma() {
    extern __shared__ char sm[];
    u32 sb = smem_u32(sm);
    const int tid = threadIdx.x, wid = tid >> 5, lane = tid & 31;
    const int n0 = blockIdx.x * NT;
    const int z = blockIdx.y;
    const int kbase = z * KCTA;

    const char* Agc = (const char*)d_A;
    const char* Bgc = (const char*)d_B;

    float acc[3][4][4];
#pragma unroll
    for (int mt = 0; mt < 3; mt++)
#pragma unroll
        for (int j = 0; j < 4; j++)
#pragma unroll
            for (int q = 0; q < 4; q++) acc[mt][j][q] = 0.0f;

    const int m_w = (wid & 1) * 48;
    const int n_off = (wid >> 1) * 32;

    // ldmatrix per-lane addresses (byte offsets within a buffer)
    // A x4 tiles: (m0k0, m8k0, m0k8, m8k8); lanes 0-7/8-15/16-23/24-31 give rows.
    const int aRow = m_w + ((lane >> 3) & 1) * 8 + (lane & 7);
    const u32 aOff = (u32)(aRow * ROWB + ((lane >> 4) & 1) * 16);
    // B x4 tiles for j-pair jp: (j0k0, j0k8, j1k0, j1k8)
    const int bRow = n_off + ((lane >> 4) & 1) * 8 + (lane & 7);
    const u32 bOff = (u32)(bRow * ROWB + ((lane >> 3) & 1) * 16);

    // per-thread fixed cp.async slots
    const int rowA = tid >> 3, wq = tid & 7;

    // ---- prologue: prefetch chunks 0 and 1 ----
#pragma unroll
    for (int pc = 0; pc < 2; pc++) {
        int kg = kbase + pc * KCH;
        u32 bufA = sb + pc * (u32)BUFSZ;
        u32 bufB = bufA + TILEA;
#pragma unroll
        for (int it = 0; it < 3; it++) {         // A: 96 rows x 8 quads
            int row = rowA + 32 * it;
            cpasync16(bufA + row * ROWB + wq * 16,
                      Agc + ((size_t)row * KTOT + kg + wq * 8) * 2);
        }
#pragma unroll
        for (int it = 0; it < 4; it++) {         // B: 128 rows x 8 quads
            int row = rowA + 32 * it;
            cpasync16(bufB + row * ROWB + wq * 16,
                      Bgc + ((size_t)(n0 + row) * KTOT + kg + wq * 8) * 2);
        }
        asm volatile("cp.async.commit_group;" ::: "memory");
    }

#pragma unroll
    for (int c = 0; c < CH; c++) {
        // 1) chunk c's copies complete (per-thread)...
        if (c < CH - 1) {
            asm volatile("cp.async.wait_group 1;" ::: "memory");
        } else {
            asm volatile("cp.async.wait_group 0;" ::: "memory");
        }
        // 2) ...and visible to every thread; also: everyone is done with buffer (c-1)%3
        __syncthreads();

        // 3) refill buffer (c+2)%3 == (c-1)%3
        if (c + 2 < CH) {
            int kg = kbase + (c + 2) * KCH;
            u32 bufA = sb + ((c + 2) % 3) * (u32)BUFSZ;
            u32 bufB = bufA + TILEA;
#pragma unroll
            for (int it = 0; it < 3; it++) {
                int row = rowA + 32 * it;
                cpasync16(bufA + row * ROWB + wq * 16,
                          Agc + ((size_t)row * KTOT + kg + wq * 8) * 2);
            }
#pragma unroll
            for (int it = 0; it < 4; it++) {
                int row = rowA + 32 * it;
                cpasync16(bufB + row * ROWB + wq * 16,
                          Bgc + ((size_t)(n0 + row) * KTOT + kg + wq * 8) * 2);
            }
            asm volatile("cp.async.commit_group;" ::: "memory");
        }

        // 4) compute chunk c
        u32 bufA = sb + (c % 3) * (u32)BUFSZ;
        u32 bufB = bufA + TILEA;

#pragma unroll
        for (int ks = 0; ks < 4; ks++) {
            u32 kcol = (u32)(ks * 32);           // 16 bf16 = 32 bytes per k-step
            u32 a[3][4];
#pragma unroll
            for (int mt = 0; mt < 3; mt++)
                ldsm4(a[mt][0], a[mt][1], a[mt][2], a[mt][3],
                      bufA + aOff + (u32)(mt * 16 * ROWB) + kcol);
#pragma unroll
            for (int jp = 0; jp < 2; jp++) {
                u32 b00, b01, b10, b11;          // (j=2jp: k0,k8), (j=2jp+1: k0,k8)
                ldsm4(b00, b01, b10, b11,
                      bufB + bOff + (u32)(jp * 16 * ROWB) + kcol);
#pragma unroll
                for (int mt = 0; mt < 3; mt++) {
                    mma16816(acc[mt][2 * jp],     a[mt][0], a[mt][1], a[mt][2], a[mt][3], b00, b01);
                    mma16816(acc[mt][2 * jp + 1], a[mt][0], a[mt][1], a[mt][2], a[mt][3], b10, b11);
                }
            }
        }
    }

    // ---- epilogue: write split-K partials (all rows < 96 by construction) ----
    const int grp = lane >> 2;
#pragma unroll
    for (int mt = 0; mt < 3; mt++) {
        int br0 = m_w + mt * 16 + grp;
        int br1 = br0 + 8;
#pragma unroll
        for (int j = 0; j < 4; j++) {
            int col = n0 + n_off + j * 8 + (lane & 3) * 2;
            *(float2*)(d_part + ((size_t)z * NB + br0) * NTOT + col) =
                make_float2(acc[mt][j][0], acc[mt][j][1]);
            *(float2*)(d_part + ((size_t)z * NB + br1) * NTOT + col) =
                make_float2(acc[mt][j][2], acc[mt][j][3]);
        }
    }
}

// ---------------- reduce + phi + Euler update + A'' split write ----------------
// One thread per (batch, neuron); (mu, s2) arrive as one float2 per z-slice.
__global__ void k_update(int first, int last, float* __restrict__ out) {
    int tid = blockIdx.x * blockDim.x + threadIdx.x;
    if (tid >= UTOT) return;
    int b = tid / NN;
    int n = tid - b * NN;

    float ms = 0.0f, ss = 0.0f, rold = 0.0f;
    if (!first) {
        rold = d_rate[tid];
        const float* pp = d_part + (size_t)b * NTOT + 2 * n;
#pragma unroll
        for (int z = 0; z < KSP; z++) {
            float2 v = *(const float2*)(pp + (size_t)z * NB * NTOT);
            ms += v.x; ss += v.y;
        }
    }
    float mu  = 0.01f * ms + d_mean[tid];
    float sig = sqrtf(0.01f * ss + 25.0f);
    float tr = (n < NE) ? 0.005f : 0.001f;
    float aT = (n < NE) ? 0.1f : 0.2f;
    float ph = phi_f(mu, sig, tr);
    float rnew = rold + aT * (ph - rold);
    d_rate[tid] = rnew;

    // A'' split: segments [ah | ah | al] matching B'' [wh | wl | wh]
    __nv_bfloat16 ah = __float2bfloat16(rnew);
    __nv_bfloat16 al = __float2bfloat16(rnew - __bfloat162float(ah));
    size_t ar = (size_t)b * KTOT + n;
    d_A[ar]            = ah;
    d_A[ar + NSEG]     = ah;
    d_A[ar + 2 * NSEG] = al;

    if (last) out[(size_t)n * NB + b] = rnew;        // out[n][b] = rate[b][n]
}

// ---------------- launch ----------------
extern "C" void kernel_launch(void* const* d_in, const int* in_sizes, int n_in,
                              void* d_out, int out_size) {
    const float* hyp = (const float*)d_in[0];
    const float* rnd = (const float*)d_in[1];
    float* out = (float*)d_out;

    cudaFuncSetAttribute(k_mma, cudaFuncAttributeMaxDynamicSharedMemorySize, SMEM_TOTAL);

    k_weightsB<<<(NSEG * NSEG + 255) / 256, 256>>>(hyp, rnd);
    k_mean<<<(NB * NN + 255) / 256, 256>>>();
    k_zeroA<<<(MM * KTOT + 255) / 256, 256>>>();

    const int UB = (UTOT + 255) / 256;
    k_update<<<UB, 256>>>(1, 0, out);                 // step 1: rate=0 -> mu=mean
    for (int s = 1; s < NSTEPS; s++) {
        k_mma<<<dim3(NTILES, KSP), 256, SMEM_TOTAL>>>();
        k_update<<<UB, 256>>>(0, s == NSTEPS - 1 ? 1 : 0, out);
    }
}

// round 12
// speedup vs baseline: 6.2635x; 1.0735x over previous
#include <cuda_runtime.h>
#include <cuda_bf16.h>
#include <math.h>
#include <cstdint>

#define NN 1500
#define NE 1200
#define NB 96
#define NSEG 1536
#define K2 3072            // storage K width: 2 segments [h | l]
#define NTOT 3072          // output rows (interleaved: 2n=mu(n), 2n+1=s2(n))
#define MM 96              // batch rows (6 x m16)
#define NT 128             // N-tile per CTA
#define NTILES 24          // NTOT/NT
#define KSP 12             // split-K over the real axis
#define KR 128             // real-k per CTA = NSEG/KSP
#define KCH 32             // real-k per smem chunk
#define CH 4               // KR/KCH
#define NSTEPS 60
#define UTOT (NB * NN)

// padded smem row: 32 bf16 data + 8 pad = 40 bf16 = 80 bytes (ldmatrix conflict-free)
#define ROWB 80
#define T_A (MM * ROWB)              // 7680
#define T_B (NT * ROWB)              // 10240
#define OFF_AH 0
#define OFF_AL T_A
#define OFF_BH (2 * T_A)
#define OFF_BL (2 * T_A + T_B)
#define BUFSZ (2 * T_A + 2 * T_B)    // 35840
#define SMEM_TOTAL (3 * BUFSZ)       // 107520 (triple buffer)

typedef unsigned int u32;
typedef unsigned long long u64;

// ---------------- static device buffers ----------------
__device__ __align__(16) __nv_bfloat16 d_A[(size_t)MM * K2];       // [b][ah|al]
__device__ __align__(16) __nv_bfloat16 d_B[(size_t)NTOT * K2];     // [r][h|l] 18.9MB
__device__ __align__(16) float d_part[(size_t)KSP * NB * NTOT];    // 14.2MB
__device__ __align__(16) float d_rate[NB * NN];
__device__ __align__(16) float d_mean[NB * NN];

__constant__ float c_contr[8] = {0.0f, 0.0432773f, 0.103411f, 0.186966f,
                                 0.303066f, 0.464386f, 0.68854f, 1.0f};

// ---------------- PTX helpers (base ISA only) ----------------
__device__ __forceinline__ u32 smem_u32(const void* p) {
    u32 a;
    asm("{ .reg .u64 t; cvta.to.shared.u64 t, %1; cvt.u32.u64 %0, t; }" : "=r"(a) : "l"(p));
    return a;
}
__device__ __forceinline__ void ldsm4(u32& r0, u32& r1, u32& r2, u32& r3, u32 addr) {
    asm volatile("ldmatrix.sync.aligned.m8n8.x4.shared.b16 {%0,%1,%2,%3}, [%4];"
                 : "=r"(r0), "=r"(r1), "=r"(r2), "=r"(r3) : "r"(addr));
}
__device__ __forceinline__ void cpasync16(u32 saddr, const void* gaddr) {
    asm volatile("cp.async.cg.shared.global [%0], [%1], 16;" :: "r"(saddr), "l"(gaddr));
}
__device__ __forceinline__ void mma16816(float* c, u32 a0, u32 a1, u32 a2, u32 a3,
                                         u32 b0, u32 b1) {
    asm volatile("mma.sync.aligned.m16n8k16.row.col.f32.bf16.bf16.f32 "
                 "{%0,%1,%2,%3}, {%4,%5,%6,%7}, {%8,%9}, {%0,%1,%2,%3};"
                 : "+f"(c[0]), "+f"(c[1]), "+f"(c[2]), "+f"(c[3])
                 : "r"(a0), "r"(a1), "r"(a2), "r"(a3), "r"(b0), "r"(b1));
}

// ---------------- math helpers ----------------
__device__ __forceinline__ float prefv(int n) {
    const float se = 179.99f / 1200.0f;
    const float si = 179.99f / 300.0f;
    return (n < NE) ? (float)n * se : (float)(n - NE) * si;
}
__device__ __forceinline__ float f_ricci(float x) {
    float z = x / (1.0f + x);
    float t = -z;
    float p = 0.14805913578876898f;
    p = p * t + 0.64290613877355551f;
    p = p * t + 1.0616084849547165f;
    p = p * t + 0.93524391761244940f;
    p = p * t + 0.62718906618071668f;
    p = p * t + 0.32171431660633076f;
    p = p * t + 0.32056016125642045f;
    p = p * t + 0.77373949685442023f;
    p = p * t + 0.22757881388024176f;
    p = p * t + 0.0f;
    return logf(2.0f * x + 1.0f) + p;
}
__device__ __forceinline__ float g_ricci(float x) {
    float z = x / (2.0f + x);
    float num = z * (3.5441754117462949f + z * (-7.0529131065835378f + z * (-56.532378057580381f
              + z * (279.56761105465944f + z * (-520.37554849441472f + z * (456.58245777026514f
              + z * (-155.73340457809226f)))))));
    float den = 1.0f + z * (-4.1357968834226053f + z * (-7.2984226138266743f + z * (98.656602235468327f
              + z * (-334.20436223415163f + z * (601.08633903294185f + z * (-599.58577549598340f
              + z * (277.18420330693891f + z * (-16.445022798669722f))))))));
    return num / den;
}
__device__ __forceinline__ float phi_f(float mu, float sig, float tau_ref) {
    const float tau = 0.01f;
    float xp = mu / sig;
    float xm = (mu - 20.0f) / sig;
    float r0;
    if (xm > 0.0f) {
        r0 = 1.0f / (f_ricci(xp) - f_ricci(xm));
    } else if (xp > 0.0f) {
        r0 = 1.0f / (f_ricci(xp) + expf(xm * xm) * g_ricci(-xm));
    } else {
        r0 = expf(-xm * xm - logf(g_ricci(-xm) - expf(xp * xp - xm * xm) * g_ricci(-xp)));
    }
    r0 = fmaxf(r0, 1e-30f);
    return 1.0f / (tau_ref + tau / r0);
}

// ---------------- setup kernels ----------------
// B row 2i   (mu neuron i): segments [wh  | wl ]
// B row 2i+1 (s2 neuron i): segments [w2h | w2l]
// A segments [ah | al]; step computes ah*wh + ah*wl + al*wh (error ~2^-18)
__global__ void k_weightsB(const float* __restrict__ hyp, const float* __restrict__ rnd) {
    int tid = blockIdx.x * blockDim.x + threadIdx.x;
    if (tid >= NSEG * NSEG) return;
    int i = tid / NSEG;          // output neuron
    int j = tid - i * NSEG;      // input neuron (K)
    float w = 0.0f;
    if (i < NN && j < NN) {
        int conn = (i >= NE ? 1 : 0) + 2 * (j >= NE ? 1 : 0);
        float J = hyp[conn], P = hyp[4 + conn], Wp = hyp[8 + conn];
        const float cd = 3.14159265358979323846f / 180.0f;
        float diff = fabsf(prefv(i) - prefv(j));
        float wden = 4.0f * (cd * Wp) * (cd * Wp);
        float z = expf((cosf(2.0f * cd * diff) - 1.0f) / wden);
        float x = 32.0f * (P * z - rnd[(size_t)i * NN + j]);
        w = J / (1.0f + expf(-x));
    }
    float w2 = w * w;
    __nv_bfloat16 wh = __float2bfloat16(w);
    __nv_bfloat16 wl = __float2bfloat16(w - __bfloat162float(wh));
    __nv_bfloat16 vh = __float2bfloat16(w2);
    __nv_bfloat16 vl = __float2bfloat16(w2 - __bfloat162float(vh));
    size_t r1 = (size_t)(2 * i) * K2;
    size_t r2 = (size_t)(2 * i + 1) * K2;
    d_B[r1 + j] = wh; d_B[r1 + NSEG + j] = wl;
    d_B[r2 + j] = vh; d_B[r2 + NSEG + j] = vl;
}

__global__ void k_mean() {
    int tid = blockIdx.x * blockDim.x + threadIdx.x;
    if (tid >= NB * NN) return;
    int b = tid / NN;
    int n = tid - b * NN;
    int c = b / 12;
    int o = b - c * 12;
    const float cd = 3.14159265358979323846f / 180.0f;
    float dth = (float)o * 15.0f - prefv(n);
    const float wden = 4.0f * (cd * 30.0f) * (cd * 30.0f);
    float cg = expf((cosf(2.0f * cd * dth) - 1.0f) / wden);
    d_mean[tid] = c_contr[c] * 20.0f * cg;
}

__global__ void k_zeroA() {
    int tid = blockIdx.x * blockDim.x + threadIdx.x;
    if (tid < MM * K2) d_A[tid] = __float2bfloat16(0.0f);
}

// ---------------- bf16 mma.sync GEMM step ----------------
// grid (24 n-tiles, 12 split-K), 256 threads.
// Per chunk (32 real-k): smem tiles Ah, Al, Bh, Bl; three MMA pairings reuse them:
//   acc += Ah*Bh + Ah*Bl + Al*Bh    (wh streamed ONCE from L2, not twice)
// Triple-buffered cp.async pipeline (distance 2, one barrier/chunk, validated R10).
__global__ __launch_bounds__(256, 2) void k_mma() {
    extern __shared__ char sm[];
    u32 sb = smem_u32(sm);
    const int tid = threadIdx.x, wid = tid >> 5, lane = tid & 31;
    const int n0 = blockIdx.x * NT;
    const int z = blockIdx.y;
    const int kbase = z * KR;          // real-k offset

    const char* Agc = (const char*)d_A;
    const char* Bgc = (const char*)d_B;

    float acc[3][4][4];
#pragma unroll
    for (int mt = 0; mt < 3; mt++)
#pragma unroll
        for (int j = 0; j < 4; j++)
#pragma unroll
            for (int q = 0; q < 4; q++) acc[mt][j][q] = 0.0f;

    const int m_w = (wid & 1) * 48;
    const int n_off = (wid >> 1) * 32;

    // ldmatrix per-lane base offsets (within a tile)
    const int aRow = m_w + ((lane >> 3) & 1) * 8 + (lane & 7);
    const u32 aOff = (u32)(aRow * ROWB + ((lane >> 4) & 1) * 16);
    const int bRow = n_off + ((lane >> 4) & 1) * 8 + (lane & 7);
    const u32 bOff = (u32)(bRow * ROWB + ((lane >> 3) & 1) * 16);

    // ---- chunk loader (h+l for A and B) ----
    auto load_chunk = [&](int c, u32 buf) {
        int kg = kbase + c * KCH;      // real-k element offset
#pragma unroll
        for (int idx = tid; idx < MM * 4; idx += 256) {        // A: 96 rows x 4 quads
            int row = idx >> 2, q = idx & 3;
            u32 so = (u32)(row * ROWB + q * 16);
            size_t go = ((size_t)row * K2 + kg + q * 8) * 2;
            cpasync16(buf + OFF_AH + so, Agc + go);
            cpasync16(buf + OFF_AL + so, Agc + go + (size_t)NSEG * 2);
        }
#pragma unroll
        for (int idx = tid; idx < NT * 4; idx += 256) {        // B: 128 rows x 4 quads
            int row = idx >> 2, q = idx & 3;
            u32 so = (u32)(row * ROWB + q * 16);
            size_t go = ((size_t)(n0 + row) * K2 + kg + q * 8) * 2;
            cpasync16(buf + OFF_BH + so, Bgc + go);
            cpasync16(buf + OFF_BL + so, Bgc + go + (size_t)NSEG * 2);
        }
        asm volatile("cp.async.commit_group;" ::: "memory");
    };

    // ---- prologue: prefetch chunks 0 and 1 ----
    load_chunk(0, sb);
    load_chunk(1, sb + BUFSZ);

#pragma unroll
    for (int c = 0; c < CH; c++) {
        if (c < CH - 1) {
            asm volatile("cp.async.wait_group 1;" ::: "memory");
        } else {
            asm volatile("cp.async.wait_group 0;" ::: "memory");
        }
        __syncthreads();
        if (c + 2 < CH) load_chunk(c + 2, sb + ((c + 2) % 3) * (u32)BUFSZ);

        u32 buf = sb + (c % 3) * (u32)BUFSZ;

#pragma unroll
        for (int ks = 0; ks < 2; ks++) {              // 32 real-k = 2 k16-steps
            u32 kcol = (u32)(ks * 32);
            u32 ah[3][4], al[3][4];
#pragma unroll
            for (int mt = 0; mt < 3; mt++) {
                u32 off = aOff + (u32)(mt * 16 * ROWB) + kcol;
                ldsm4(ah[mt][0], ah[mt][1], ah[mt][2], ah[mt][3], buf + OFF_AH + off);
                ldsm4(al[mt][0], al[mt][1], al[mt][2], al[mt][3], buf + OFF_AL + off);
            }
#pragma unroll
            for (int jp = 0; jp < 2; jp++) {
                u32 off = bOff + (u32)(jp * 16 * ROWB) + kcol;
                u32 h00, h01, h10, h11, l00, l01, l10, l11;
                ldsm4(h00, h01, h10, h11, buf + OFF_BH + off);
                ldsm4(l00, l01, l10, l11, buf + OFF_BL + off);
#pragma unroll
                for (int mt = 0; mt < 3; mt++) {
                    // pairing 1: Ah * Bh
                    mma16816(acc[mt][2 * jp],     ah[mt][0], ah[mt][1], ah[mt][2], ah[mt][3], h00, h01);
                    mma16816(acc[mt][2 * jp + 1], ah[mt][0], ah[mt][1], ah[mt][2], ah[mt][3], h10, h11);
                    // pairing 2: Ah * Bl
                    mma16816(acc[mt][2 * jp],     ah[mt][0], ah[mt][1], ah[mt][2], ah[mt][3], l00, l01);
                    mma16816(acc[mt][2 * jp + 1], ah[mt][0], ah[mt][1], ah[mt][2], ah[mt][3], l10, l11);
                    // pairing 3: Al * Bh
                    mma16816(acc[mt][2 * jp],     al[mt][0], al[mt][1], al[mt][2], al[mt][3], h00, h01);
                    mma16816(acc[mt][2 * jp + 1], al[mt][0], al[mt][1], al[mt][2], al[mt][3], h10, h11);
                }
            }
        }
    }

    // ---- epilogue: write split-K partials ----
    const int grp = lane >> 2;
#pragma unroll
    for (int mt = 0; mt < 3; mt++) {
        int br0 = m_w + mt * 16 + grp;
        int br1 = br0 + 8;
#pragma unroll
        for (int j = 0; j < 4; j++) {
            int col = n0 + n_off + j * 8 + (lane & 3) * 2;
            *(float2*)(d_part + ((size_t)z * NB + br0) * NTOT + col) =
                make_float2(acc[mt][j][0], acc[mt][j][1]);
            *(float2*)(d_part + ((size_t)z * NB + br1) * NTOT + col) =
                make_float2(acc[mt][j][2], acc[mt][j][3]);
        }
    }
}

// ---------------- reduce + phi + Euler update + A split write ----------------
__global__ void k_update(int first, int last, float* __restrict__ out) {
    int tid = blockIdx.x * blockDim.x + threadIdx.x;
    if (tid >= UTOT) return;
    int b = tid / NN;
    int n = tid - b * NN;

    float ms = 0.0f, ss = 0.0f, rold = 0.0f;
    if (!first) {
        rold = d_rate[tid];
        const float* pp = d_part + (size_t)b * NTOT + 2 * n;
#pragma unroll
        for (int z = 0; z < KSP; z++) {
            float2 v = *(const float2*)(pp + (size_t)z * NB * NTOT);
            ms += v.x; ss += v.y;
        }
    }
    float mu  = 0.01f * ms + d_mean[tid];
    float sig = sqrtf(0.01f * ss + 25.0f);
    float tr = (n < NE) ? 0.005f : 0.001f;
    float aT = (n < NE) ? 0.1f : 0.2f;
    float ph = phi_f(mu, sig, tr);
    float rnew = rold + aT * (ph - rold);
    d_rate[tid] = rnew;

    __nv_bfloat16 ah = __float2bfloat16(rnew);
    __nv_bfloat16 al = __float2bfloat16(rnew - __bfloat162float(ah));
    size_t ar = (size_t)b * K2 + n;
    d_A[ar]        = ah;
    d_A[ar + NSEG] = al;

    if (last) out[(size_t)n * NB + b] = rnew;        // out[n][b] = rate[b][n]
}

// ---------------- launch ----------------
extern "C" void kernel_launch(void* const* d_in, const int* in_sizes, int n_in,
                              void* d_out, int out_size) {
    const float* hyp = (const float*)d_in[0];
    const float* rnd = (const float*)d_in[1];
    float* out = (float*)d_out;

    cudaFuncSetAttribute(k_mma, cudaFuncAttributeMaxDynamicSharedMemorySize, SMEM_TOTAL);

    k_weightsB<<<(NSEG * NSEG + 255) / 256, 256>>>(hyp, rnd);
    k_mean<<<(NB * NN + 255) / 256, 256>>>();
    k_zeroA<<<(MM * K2 + 255) / 256, 256>>>();

    const int UB = (UTOT + 255) / 256;
    k_update<<<UB, 256>>>(1, 0, out);                 // step 1: rate=0 -> mu=mean
    for (int s = 1; s < NSTEPS; s++) {
        k_mma<<<dim3(NTILES, KSP), 256, SMEM_TOTAL>>>();
        k_update<<<UB, 256>>>(0, s == NSTEPS - 1 ? 1 : 0, out);
    }
}